// round 1
// baseline (speedup 1.0000x reference)
#include <cuda_runtime.h>

#define B_ 4
#define N_ 32768
#define C_ 256
#define H_ 8
#define CH_ 64
#define M_ 64
#define INNER_ 512
#define ROWS_ (B_*N_)          // 131072
#define BH_ (B_*H_)            // 32
#define TK_CHUNK 2048

// ---------------- scratch (static device allocations; no cudaMalloc) ----------------
__device__ float d_proj[(size_t)ROWS_ * 1024];         // [row][0:512 fx | 512:1024 xm]  (512 MB)
__device__ float d_sw[(size_t)BH_ * N_ * M_];          // [b][h][n][m] softmax-over-M     (256 MB)
__device__ float d_tokx[BH_ * M_ * CH_];               // un-normalized token (x)
__device__ float d_tokc[BH_ * M_ * CH_];               // un-normalized token (x_cross)
__device__ float d_csx[BH_ * M_];                      // colsum over N (x)
__device__ float d_csc[BH_ * M_];                      // colsum over N (x_cross)
__device__ float d_outsc[BH_ * M_ * CH_];              // out_tok / (colsum_x + eps)
__device__ float d_wot[B_ * INNER_ * C_];              // [b][(h*64+g)][c]

// ---------------- zero init (re-run every launch: deterministic) ----------------
__global__ void zero_kernel() {
    int i = blockIdx.x * blockDim.x + threadIdx.x;
    if (i < BH_ * M_ * CH_) { d_tokx[i] = 0.f; d_tokc[i] = 0.f; }
    if (i < BH_ * M_)       { d_csx[i]  = 0.f; d_csc[i]  = 0.f; }
}

// ---------------- projection GEMM: d_proj[:, outoff:outoff+512] = X @ W + bias ----------------
// X: [ROWS_, 256], W: [256, 512], BM=128 BN=64 BK=16, 256 threads, thread tile 8x4
__global__ __launch_bounds__(256) void proj_gemm(const float* __restrict__ X,
                                                 const float* __restrict__ W,
                                                 const float* __restrict__ bias,
                                                 int outoff) {
    __shared__ float AsT[16][132];
    __shared__ float Bs[16][64];
    const int t  = threadIdx.x;
    const int m0 = blockIdx.y * 128;
    const int j0 = blockIdx.x * 64;
    const int ty = t >> 4;             // 0..15 (rows)
    const int tx = t & 15;             // 0..15 (cols)
    const int ar = t >> 2;             // 0..63
    const int ac = (t & 3) * 4;        // 0,4,8,12
    const int bk = t >> 4;             // 0..15
    const int bc = (t & 15) * 4;

    float acc[8][4];
#pragma unroll
    for (int i = 0; i < 8; i++)
#pragma unroll
        for (int j = 0; j < 4; j++) acc[i][j] = 0.f;

    for (int k0 = 0; k0 < 256; k0 += 16) {
#pragma unroll
        for (int l = 0; l < 2; l++) {
            int row = l * 64 + ar;
            float4 v = *(const float4*)&X[(size_t)(m0 + row) * 256 + k0 + ac];
            AsT[ac + 0][row] = v.x; AsT[ac + 1][row] = v.y;
            AsT[ac + 2][row] = v.z; AsT[ac + 3][row] = v.w;
        }
        *(float4*)&Bs[bk][bc] = *(const float4*)&W[(size_t)(k0 + bk) * 512 + j0 + bc];
        __syncthreads();
#pragma unroll
        for (int kk = 0; kk < 16; kk++) {
            float a[8], b[4];
#pragma unroll
            for (int i = 0; i < 8; i++) a[i] = AsT[kk][ty * 8 + i];
#pragma unroll
            for (int j = 0; j < 4; j++) b[j] = Bs[kk][tx * 4 + j];
#pragma unroll
            for (int i = 0; i < 8; i++)
#pragma unroll
                for (int j = 0; j < 4; j++) acc[i][j] += a[i] * b[j];
        }
        __syncthreads();
    }
#pragma unroll
    for (int i = 0; i < 8; i++) {
        int row = m0 + ty * 8 + i;
        int col = j0 + tx * 4;
        float4 o;
        o.x = acc[i][0] + bias[col + 0];
        o.y = acc[i][1] + bias[col + 1];
        o.z = acc[i][2] + bias[col + 2];
        o.w = acc[i][3] + bias[col + 3];
        *(float4*)&d_proj[(size_t)row * 1024 + outoff + col] = o;
    }
}

// ---------------- per-row slice logits + softmax over M; writes d_sw ----------------
__global__ __launch_bounds__(256) void softmax_kernel(const float* __restrict__ Wslice,
                                                      const float* __restrict__ bslice,
                                                      const float* __restrict__ temperature) {
    const int row = blockIdx.x;        // 0..ROWS_-1
    const int b = row >> 15;           // row / N_
    const int n = row & (N_ - 1);
    const int t = threadIdx.x;
    __shared__ float xm[512];
    __shared__ float lg[512];
    xm[t]       = d_proj[(size_t)row * 1024 + 512 + t];
    xm[t + 256] = d_proj[(size_t)row * 1024 + 768 + t];
    __syncthreads();
#pragma unroll
    for (int rep = 0; rep < 2; rep++) {
        int j = t + rep * 256;
        int h = j >> 6, m = j & 63;
        float accv = bslice[m];
        const float* xh = &xm[h * 64];
#pragma unroll 16
        for (int c = 0; c < 64; c++) accv += xh[c] * Wslice[c * 64 + m];
        float tp = temperature[h];
        tp = fminf(fmaxf(tp, 0.1f), 5.0f);
        lg[j] = accv / tp;
    }
    __syncthreads();
    const int w = t >> 5, lane = t & 31;   // warp w == head w
    float v0 = lg[w * 64 + lane], v1 = lg[w * 64 + 32 + lane];
    float mx = fmaxf(v0, v1);
#pragma unroll
    for (int o = 16; o; o >>= 1) mx = fmaxf(mx, __shfl_xor_sync(0xffffffffu, mx, o));
    float e0 = __expf(v0 - mx), e1 = __expf(v1 - mx);
    float s = e0 + e1;
#pragma unroll
    for (int o = 16; o; o >>= 1) s += __shfl_xor_sync(0xffffffffu, s, o);
    float inv = 1.f / s;
    size_t base = ((size_t)(b * H_ + w) * N_ + n) * 64;
    d_sw[base + lane]      = e0 * inv;
    d_sw[base + 32 + lane] = e1 * inv;
}

// ---------------- token aggregation: token[g][c] += sw[n][g]*fx[n][c]; colsum[g] += sw ----------------
__global__ __launch_bounds__(256) void token_kernel(int which_x) {
    float* tok = which_x ? d_tokx : d_tokc;
    float* cs  = which_x ? d_csx  : d_csc;
    const int bh = blockIdx.y;
    const int b = bh >> 3, h = bh & 7;
    const int n0 = blockIdx.x * TK_CHUNK;
    const int t = threadIdx.x;
    __shared__ float sws[16][64];
    __shared__ float fxs[16][64];
    const int lr = t >> 4;             // 0..15
    const int lc = (t & 15) * 4;
    const int gq = t & 15, cq = t >> 4;
    float acc[4][4];
#pragma unroll
    for (int i = 0; i < 4; i++)
#pragma unroll
        for (int j = 0; j < 4; j++) acc[i][j] = 0.f;
    float csacc = 0.f;

    for (int nn = 0; nn < TK_CHUNK; nn += 16) {
        int n = n0 + nn + lr;
        *(float4*)&sws[lr][lc] = *(const float4*)&d_sw[((size_t)bh * N_ + n) * 64 + lc];
        *(float4*)&fxs[lr][lc] = *(const float4*)&d_proj[((size_t)(b * N_ + n)) * 1024 + h * 64 + lc];
        __syncthreads();
#pragma unroll
        for (int kk = 0; kk < 16; kk++) {
            float a[4], bb[4];
#pragma unroll
            for (int i = 0; i < 4; i++) a[i] = sws[kk][gq * 4 + i];
#pragma unroll
            for (int j = 0; j < 4; j++) bb[j] = fxs[kk][cq * 4 + j];
#pragma unroll
            for (int i = 0; i < 4; i++)
#pragma unroll
                for (int j = 0; j < 4; j++) acc[i][j] += a[i] * bb[j];
        }
        if (t < 64) {
#pragma unroll
            for (int kk = 0; kk < 16; kk++) csacc += sws[kk][t];
        }
        __syncthreads();
    }
#pragma unroll
    for (int i = 0; i < 4; i++)
#pragma unroll
        for (int j = 0; j < 4; j++)
            atomicAdd(&tok[bh * 4096 + (gq * 4 + i) * 64 + cq * 4 + j], acc[i][j]);
    if (t < 64) atomicAdd(&cs[bh * 64 + t], csacc);
}

// ---------------- tiny M=64 attention per (b,h): q/k/v, softmax, out_tok, fold 1/colsum ----------------
__global__ void attn_kernel(const float* __restrict__ Wq,
                            const float* __restrict__ Wk,
                            const float* __restrict__ Wv) {
    extern __shared__ float sm[];
    float* A  = sm;                    // [64][65]
    float* Ks = sm + 64 * 65;          // [64][64]
    float* Vs = Ks + 64 * 64;          // [64][64]
    const int bh = blockIdx.x;
    const int g = threadIdx.x;         // 64 threads

    // normalized token_c into A
    for (int idx = g; idx < 4096; idx += 64) {
        int r = idx >> 6, c = idx & 63;
        A[r * 65 + c] = d_tokc[bh * 4096 + idx] / (d_csc[bh * 64 + r] + 1e-5f);
    }
    __syncthreads();
    {
        float ka[64], va[64];
#pragma unroll
        for (int c = 0; c < 64; c++) { ka[c] = 0.f; va[c] = 0.f; }
        for (int e = 0; e < 64; e++) {
            float te = A[g * 65 + e];
#pragma unroll
            for (int c = 0; c < 64; c++) {
                ka[c] += te * Wk[e * 64 + c];
                va[c] += te * Wv[e * 64 + c];
            }
        }
#pragma unroll
        for (int c = 0; c < 64; c++) { Ks[g * 64 + c] = ka[c]; Vs[g * 64 + c] = va[c]; }
    }
    __syncthreads();
    // normalized token_x into A
    for (int idx = g; idx < 4096; idx += 64) {
        int r = idx >> 6, c = idx & 63;
        A[r * 65 + c] = d_tokx[bh * 4096 + idx] / (d_csx[bh * 64 + r] + 1e-5f);
    }
    __syncthreads();

    float q[64];
#pragma unroll
    for (int c = 0; c < 64; c++) q[c] = 0.f;
    for (int e = 0; e < 64; e++) {
        float te = A[g * 65 + e];
#pragma unroll
        for (int c = 0; c < 64; c++) q[c] += te * Wq[e * 64 + c];
    }
    __syncthreads();                   // A free again; reuse row g as score row
    float* srow = &A[g * 65];
    float mx = -1e30f;
    for (int m = 0; m < 64; m++) {
        float a2 = 0.f;
#pragma unroll
        for (int c = 0; c < 64; c++) a2 += q[c] * Ks[m * 64 + c];
        a2 *= 0.125f;                  // CH^-0.5
        srow[m] = a2;
        mx = fmaxf(mx, a2);
    }
    float sum = 0.f;
    for (int m = 0; m < 64; m++) { float e = __expf(srow[m] - mx); srow[m] = e; sum += e; }
    float inv = 1.f / sum;
    float o[64];
#pragma unroll
    for (int c = 0; c < 64; c++) o[c] = 0.f;
    for (int m = 0; m < 64; m++) {
        float p = srow[m] * inv;
#pragma unroll
        for (int c = 0; c < 64; c++) o[c] += p * Vs[m * 64 + c];
    }
    float invx = 1.f / (d_csx[bh * 64 + g] + 1e-5f);
#pragma unroll
    for (int c = 0; c < 64; c++) d_outsc[bh * 4096 + g * 64 + c] = o[c] * invx;
}

// ---------------- Wot[b,(h,g),:] = sum_c outsc[b,h,g,c] * Wo[h*64+c,:] ----------------
__global__ __launch_bounds__(256) void wot_kernel(const float* __restrict__ Wo) {
    const int bhg = blockIdx.x;                 // 2048 = B*H*M
    const int hg = bhg & (H_ * M_ - 1);
    const int h = hg >> 6;
    __shared__ float orow[64];
    const int t = threadIdx.x;
    if (t < 64) orow[t] = d_outsc[bhg * 64 + t];
    __syncthreads();
    float acc = 0.f;
#pragma unroll 8
    for (int c = 0; c < 64; c++) acc += orow[c] * Wo[(h * 64 + c) * 256 + t];
    d_wot[(size_t)bhg * 256 + t] = acc;
}

// ---------------- final: out[b] = sw[b] (N x 512) @ Wot[b] (512 x 256) + bo ----------------
// BM=64 BN=64 BK=32, 256 threads, thread tile 4x4
__global__ __launch_bounds__(256) void final_gemm(const float* __restrict__ bo,
                                                  float* __restrict__ out) {
    __shared__ float AsT[32][68];
    __shared__ float Bs[32][64];
    const int b  = blockIdx.z;
    const int n0 = blockIdx.y * 64;
    const int c0 = blockIdx.x * 64;
    const int t  = threadIdx.x;
    const int ry = t >> 4, cx = t & 15;
    const int ar = t >> 3;              // 0..31
    const int ak = (t & 7) * 4;         // 0..28
    const int bk = t >> 4;              // 0..15
    const int bc2 = (t & 15) * 4;

    float acc[4][4];
#pragma unroll
    for (int i = 0; i < 4; i++)
#pragma unroll
        for (int j = 0; j < 4; j++) acc[i][j] = 0.f;

    for (int k0 = 0; k0 < 512; k0 += 32) {
        const int h = k0 >> 6;
        const int g0 = k0 & 63;
#pragma unroll
        for (int l = 0; l < 2; l++) {
            int r = l * 32 + ar;        // 0..63
            float4 v = *(const float4*)&d_sw[((size_t)(b * H_ + h) * N_ + n0 + r) * 64 + g0 + ak];
            AsT[ak + 0][r] = v.x; AsT[ak + 1][r] = v.y;
            AsT[ak + 2][r] = v.z; AsT[ak + 3][r] = v.w;
        }
#pragma unroll
        for (int l = 0; l < 2; l++) {
            int kk = l * 16 + bk;
            *(float4*)&Bs[kk][bc2] = *(const float4*)&d_wot[((size_t)b * 512 + k0 + kk) * 256 + c0 + bc2];
        }
        __syncthreads();
#pragma unroll
        for (int kk = 0; kk < 32; kk++) {
            float a[4], bb[4];
#pragma unroll
            for (int i = 0; i < 4; i++) a[i] = AsT[kk][ry * 4 + i];
#pragma unroll
            for (int j = 0; j < 4; j++) bb[j] = Bs[kk][cx * 4 + j];
#pragma unroll
            for (int i = 0; i < 4; i++)
#pragma unroll
                for (int j = 0; j < 4; j++) acc[i][j] += a[i] * bb[j];
        }
        __syncthreads();
    }
#pragma unroll
    for (int i = 0; i < 4; i++) {
        int row = n0 + ry * 4 + i;
        int col = c0 + cx * 4;
        float4 o;
        o.x = acc[i][0] + bo[col + 0];
        o.y = acc[i][1] + bo[col + 1];
        o.z = acc[i][2] + bo[col + 2];
        o.w = acc[i][3] + bo[col + 3];
        *(float4*)&out[((size_t)(b * N_) + row) * 256 + col] = o;
    }
}

// ---------------- launcher ----------------
extern "C" void kernel_launch(void* const* d_in, const int* in_sizes, int n_in,
                              void* d_out, int out_size) {
    const float* x      = (const float*)d_in[0];
    const float* xc     = (const float*)d_in[1];
    const float* Wfx    = (const float*)d_in[2];
    const float* bfx    = (const float*)d_in[3];
    const float* Wx     = (const float*)d_in[4];
    const float* bx     = (const float*)d_in[5];
    const float* Wslice = (const float*)d_in[6];
    const float* bslice = (const float*)d_in[7];
    const float* temp   = (const float*)d_in[8];
    const float* Wq     = (const float*)d_in[9];
    const float* Wk     = (const float*)d_in[10];
    const float* Wv     = (const float*)d_in[11];
    const float* Wo     = (const float*)d_in[12];
    const float* bo     = (const float*)d_in[13];
    float* out = (float*)d_out;

    const int attn_smem = (64 * 65 + 2 * 64 * 64) * (int)sizeof(float);   // 49408 B
    cudaFuncSetAttribute(attn_kernel, cudaFuncAttributeMaxDynamicSharedMemorySize, attn_smem);

    zero_kernel<<<512, 256>>>();

    dim3 pgrid(8, ROWS_ / 128);
    dim3 tgrid(N_ / TK_CHUNK, BH_);

    // ---- cross pass (token_c) ----
    proj_gemm<<<pgrid, 256>>>(xc, Wfx, bfx, 0);
    proj_gemm<<<pgrid, 256>>>(xc, Wx, bx, 512);
    softmax_kernel<<<ROWS_, 256>>>(Wslice, bslice, temp);
    token_kernel<<<tgrid, 256>>>(0);

    // ---- x pass (token_x; d_sw kept for epilogue) ----
    proj_gemm<<<pgrid, 256>>>(x, Wfx, bfx, 0);
    proj_gemm<<<pgrid, 256>>>(x, Wx, bx, 512);
    softmax_kernel<<<ROWS_, 256>>>(Wslice, bslice, temp);
    token_kernel<<<tgrid, 256>>>(1);

    // ---- tiny attention + output refactor ----
    attn_kernel<<<BH_, 64, attn_smem>>>(Wq, Wk, Wv);
    wot_kernel<<<B_ * H_ * M_, 256>>>(Wo);
    final_gemm<<<dim3(C_ / 64, N_ / 64, B_), 256>>>(bo, out);
}

// round 3
// speedup vs baseline: 2.0798x; 2.0798x over previous
#include <cuda_runtime.h>
#include <cuda_bf16.h>
#include <cstdint>

#define B_ 4
#define N_ 32768
#define C_ 256
#define H_ 8
#define CH_ 64
#define M_ 64
#define INNER_ 512
#define ROWS_ (B_*N_)          // 131072
#define BH_ (B_*H_)            // 32
#define TK_CHUNK 2048

// ================= static scratch =================
__device__ float d_fx[(size_t)ROWS_ * 512];            // x@Wfx+bfx
__device__ float d_sw[(size_t)BH_ * N_ * M_];          // softmax weights
__device__ float d_tokx[BH_ * M_ * CH_];
__device__ float d_tokc[BH_ * M_ * CH_];
__device__ float d_csx[BH_ * M_];
__device__ float d_csc[BH_ * M_];
__device__ float d_outsc[BH_ * M_ * CH_];
__device__ float d_wot[B_ * INNER_ * C_];
__device__ float d_bls[INNER_];
__device__ __nv_bfloat16 d_wfx_h[INNER_ * C_];         // Wfx^T split  [512][256]
__device__ __nv_bfloat16 d_wfx_l[INNER_ * C_];
__device__ __nv_bfloat16 d_wls_h[INNER_ * C_];         // (Wx@Wslice)^T split [512][256]
__device__ __nv_bfloat16 d_wls_l[INNER_ * C_];
__device__ __nv_bfloat16 d_wot_h[B_ * C_ * INNER_];    // wot^T split [b][256][512]
__device__ __nv_bfloat16 d_wot_l[B_ * C_ * INNER_];

// ================= helpers =================
__device__ __forceinline__ uint32_t smem_u32(const void* p) {
    uint32_t a;
    asm("{ .reg .u64 t; cvta.to.shared.u64 t, %1; cvt.u32.u64 %0, t; }" : "=r"(a) : "l"(p));
    return a;
}
__device__ __forceinline__ void ldsm4(uint32_t* r, uint32_t addr) {
    asm volatile("ldmatrix.sync.aligned.m8n8.x4.shared.b16 {%0,%1,%2,%3}, [%4];"
                 : "=r"(r[0]), "=r"(r[1]), "=r"(r[2]), "=r"(r[3]) : "r"(addr));
}
__device__ __forceinline__ void mma16816(float* c, const uint32_t* a, const uint32_t* b) {
    asm volatile("mma.sync.aligned.m16n8k16.row.col.f32.bf16.bf16.f32 "
                 "{%0,%1,%2,%3}, {%4,%5,%6,%7}, {%8,%9}, {%0,%1,%2,%3};"
                 : "+f"(c[0]), "+f"(c[1]), "+f"(c[2]), "+f"(c[3])
                 : "r"(a[0]), "r"(a[1]), "r"(a[2]), "r"(a[3]), "r"(b[0]), "r"(b[1]));
}
__device__ __forceinline__ void split2(float x, float y, uint32_t& hi, uint32_t& lo) {
    __nv_bfloat16 hx = __float2bfloat16(x), hy = __float2bfloat16(y);
    float rx = x - __bfloat162float(hx), ry = y - __bfloat162float(hy);
    __nv_bfloat16 lx = __float2bfloat16(rx), ly = __float2bfloat16(ry);
    hi = (uint32_t)__bfloat16_as_ushort(hx) | ((uint32_t)__bfloat16_as_ushort(hy) << 16);
    lo = (uint32_t)__bfloat16_as_ushort(lx) | ((uint32_t)__bfloat16_as_ushort(ly) << 16);
}

// smem layout for GEMM kernels (64 KB dynamic):
//   [0      :16384) A_hi   128 rows x 128B (bf16 k-chunk of 64)
//   [16384  :32768) A_lo
//   [32768  :49152) B_hi   128 rows x 128B
//   [49152  :65536) B_lo
#define GEMM_SMEM 65536
#define SWX(r, byte) ((uint32_t)((r) * 128 + ((byte) ^ (((r) & 7) << 4))))

// ===================================================================
// Shared mainloop machinery (macro-expanded in each kernel).
// Warp layout: 8 warps; warp_m = w&3 (rows, 32 each), warp_n = w>>2 (cols, 64 each)
// ===================================================================
#define GEMM_PROLOG() \
    extern __shared__ char smem[]; \
    const uint32_t sb = smem_u32(smem); \
    const int t = threadIdx.x; \
    const int w = t >> 5, lane = t & 31; \
    const int wm = (w & 3) * 32, wn = (w >> 2) * 64; \
    const int g = lane >> 2, tq = lane & 3; \
    const int ar_ = lane & 15, akh_ = lane >> 4; \
    const int qd_ = lane >> 3, bl8_ = lane & 7; \
    uint32_t abase[2], axr[2], bbase[4], bxr[4]; \
    _Pragma("unroll") for (int mi = 0; mi < 2; mi++) { \
        int row = wm + mi * 16 + ar_; \
        abase[mi] = row * 128; axr[mi] = (row & 7) << 4; \
    } \
    _Pragma("unroll") for (int nb = 0; nb < 4; nb++) { \
        int row = wn + nb * 16 + (qd_ >> 1) * 8 + bl8_; \
        bbase[nb] = row * 128; bxr[nb] = (row & 7) << 4; \
    } \
    const uint32_t bk16_ = (qd_ & 1) * 16; \
    const uint32_t ak16_ = akh_ * 16; \
    float c[2][8][4]; \
    _Pragma("unroll") for (int mi = 0; mi < 2; mi++) \
    _Pragma("unroll") for (int ni = 0; ni < 8; ni++) \
    _Pragma("unroll") for (int q = 0; q < 4; q++) c[mi][ni][q] = 0.f;

#define GEMM_COMPUTE_CHUNK() \
    __syncthreads(); \
    _Pragma("unroll") for (int ks = 0; ks < 4; ks++) { \
        uint32_t ah[2][4], al[2][4], bh[8][2], bl[8][2]; \
        const uint32_t ka = ks * 32 + ak16_; \
        const uint32_t kb = ks * 32 + bk16_; \
        _Pragma("unroll") for (int mi = 0; mi < 2; mi++) { \
            uint32_t off = abase[mi] + (ka ^ axr[mi]); \
            ldsm4(ah[mi], sb + off); \
            ldsm4(al[mi], sb + 16384 + off); \
        } \
        _Pragma("unroll") for (int nb = 0; nb < 4; nb++) { \
            uint32_t off = bbase[nb] + (kb ^ bxr[nb]); \
            uint32_t rh[4], rl[4]; \
            ldsm4(rh, sb + 32768 + off); \
            ldsm4(rl, sb + 49152 + off); \
            bh[nb*2][0] = rh[0]; bh[nb*2][1] = rh[1]; \
            bh[nb*2+1][0] = rh[2]; bh[nb*2+1][1] = rh[3]; \
            bl[nb*2][0] = rl[0]; bl[nb*2][1] = rl[1]; \
            bl[nb*2+1][0] = rl[2]; bl[nb*2+1][1] = rl[3]; \
        } \
        _Pragma("unroll") for (int mi = 0; mi < 2; mi++) \
        _Pragma("unroll") for (int ni = 0; ni < 8; ni++) { \
            mma16816(c[mi][ni], ah[mi], bh[ni]); \
            mma16816(c[mi][ni], ah[mi], bl[ni]); \
            mma16816(c[mi][ni], al[mi], bh[ni]); \
        } \
    } \
    __syncthreads();

// Load A chunk (fp32 source, row-stride 256) + B chunk ([N][256] bf16 pair)
#define LOAD_A_X(Xp, m0, k0) \
    _Pragma("unroll") for (int i = 0; i < 8; i++) { \
        int e = i * 256 + t, r = e >> 4, q = e & 15; \
        float4 v = *(const float4*)&(Xp)[(size_t)((m0) + r) * 256 + (k0) + q * 4]; \
        uint2 hh, ll; \
        split2(v.x, v.y, hh.x, ll.x); \
        split2(v.z, v.w, hh.y, ll.y); \
        uint32_t off = SWX(r, q * 8); \
        *(uint2*)(smem + off) = hh; \
        *(uint2*)(smem + 16384 + off) = ll; \
    }
#define LOAD_B_256(Bhp, Blp, j0, k0) \
    _Pragma("unroll") for (int i = 0; i < 4; i++) { \
        int e = i * 256 + t, r = e >> 3, q = e & 7; \
        uint32_t off = SWX(r, q * 16); \
        *(uint4*)(smem + 32768 + off) = *(const uint4*)&(Bhp)[(size_t)((j0) + r) * 256 + (k0) + q * 8]; \
        *(uint4*)(smem + 49152 + off) = *(const uint4*)&(Blp)[(size_t)((j0) + r) * 256 + (k0) + q * 8]; \
    }

// ================= GEMM 1: d_fx = X @ Wfx + bfx =================
__global__ __launch_bounds__(256) void fx_mma(const float* __restrict__ X,
                                              const float* __restrict__ bias) {
    GEMM_PROLOG();
    const int m0 = blockIdx.y * 128;
    const int j0 = blockIdx.x * 128;
    for (int ch = 0; ch < 4; ch++) {
        const int k0 = ch * 64;
        LOAD_A_X(X, m0, k0);
        LOAD_B_256(d_wfx_h, d_wfx_l, j0, k0);
        GEMM_COMPUTE_CHUNK();
    }
#pragma unroll
    for (int mi = 0; mi < 2; mi++) {
        int row0 = m0 + wm + mi * 16 + g;
#pragma unroll
        for (int ni = 0; ni < 8; ni++) {
            int col = j0 + wn + ni * 8 + tq * 2;
            float2 bb = *(const float2*)&bias[col];
            float2 o0 = { c[mi][ni][0] + bb.x, c[mi][ni][1] + bb.y };
            float2 o1 = { c[mi][ni][2] + bb.x, c[mi][ni][3] + bb.y };
            *(float2*)&d_fx[(size_t)row0 * 512 + col] = o0;
            *(float2*)&d_fx[(size_t)(row0 + 8) * 512 + col] = o1;
        }
    }
}

// ================= GEMM 2: logits = X @ Wls + bls, fused softmax -> d_sw =================
__global__ __launch_bounds__(256) void logit_mma(const float* __restrict__ X,
                                                 const float* __restrict__ temperature) {
    GEMM_PROLOG();
    const int m0 = blockIdx.y * 128;
    const int j0 = blockIdx.x * 128;
    for (int ch = 0; ch < 4; ch++) {
        const int k0 = ch * 64;
        LOAD_A_X(X, m0, k0);
        LOAD_B_256(d_wls_h, d_wls_l, j0, k0);
        GEMM_COMPUTE_CHUNK();
    }
    // epilogue: this warp owns head h's full 64 columns for its 32 rows
    const int h = (j0 >> 6) + (w >> 2);
    float tp = temperature[h];
    tp = fminf(fmaxf(tp, 0.1f), 5.0f);
    const float invt = 1.f / tp;
    float2 blv[8];
#pragma unroll
    for (int ni = 0; ni < 8; ni++)
        blv[ni] = *(const float2*)&d_bls[j0 + wn + ni * 8 + tq * 2];
#pragma unroll
    for (int mi = 0; mi < 2; mi++)
#pragma unroll
        for (int ni = 0; ni < 8; ni++) {
            c[mi][ni][0] = (c[mi][ni][0] + blv[ni].x) * invt;
            c[mi][ni][1] = (c[mi][ni][1] + blv[ni].y) * invt;
            c[mi][ni][2] = (c[mi][ni][2] + blv[ni].x) * invt;
            c[mi][ni][3] = (c[mi][ni][3] + blv[ni].y) * invt;
        }
#pragma unroll
    for (int mi = 0; mi < 2; mi++)
#pragma unroll
        for (int half = 0; half < 2; half++) {
            const int ci = half * 2;
            float mx = -1e30f;
#pragma unroll
            for (int ni = 0; ni < 8; ni++)
                mx = fmaxf(mx, fmaxf(c[mi][ni][ci], c[mi][ni][ci + 1]));
            mx = fmaxf(mx, __shfl_xor_sync(0xffffffffu, mx, 1));
            mx = fmaxf(mx, __shfl_xor_sync(0xffffffffu, mx, 2));
            float s = 0.f;
#pragma unroll
            for (int ni = 0; ni < 8; ni++) {
                float e0 = __expf(c[mi][ni][ci] - mx);
                float e1 = __expf(c[mi][ni][ci + 1] - mx);
                c[mi][ni][ci] = e0; c[mi][ni][ci + 1] = e1;
                s += e0 + e1;
            }
            s += __shfl_xor_sync(0xffffffffu, s, 1);
            s += __shfl_xor_sync(0xffffffffu, s, 2);
            float inv = 1.f / s;
            int row = m0 + wm + mi * 16 + half * 8 + g;
            int b = row >> 15, n = row & (N_ - 1);
            size_t base = ((size_t)(b * H_ + h) * N_ + n) * 64;
#pragma unroll
            for (int ni = 0; ni < 8; ni++) {
                float2 o = { c[mi][ni][ci] * inv, c[mi][ni][ci + 1] * inv };
                *(float2*)&d_sw[base + ni * 8 + tq * 2] = o;
            }
        }
}

// ================= GEMM 3: out[b] = sw[b] (N x 512) @ wot[b] (512 x 256) + bo =================
__global__ __launch_bounds__(256) void final_mma(const float* __restrict__ bo,
                                                 float* __restrict__ out) {
    GEMM_PROLOG();
    const int m0 = blockIdx.y * 128;
    const int j0 = blockIdx.x * 128;
    const int bb_ = m0 >> 15;
    const __nv_bfloat16* Bh = d_wot_h + (size_t)bb_ * 256 * 512;
    const __nv_bfloat16* Bl = d_wot_l + (size_t)bb_ * 256 * 512;
    for (int ch = 0; ch < 8; ch++) {
        const int k0 = ch * 64;
        // A chunk: sw head ch, rows m0..m0+127 (same batch), 64 slice cols
#pragma unroll
        for (int i = 0; i < 8; i++) {
            int e = i * 256 + t, r = e >> 4, q = e & 15;
            int n = (m0 + r) & (N_ - 1);
            float4 v = *(const float4*)&d_sw[((size_t)(bb_ * H_ + ch) * N_ + n) * 64 + q * 4];
            uint2 hh, ll;
            split2(v.x, v.y, hh.x, ll.x);
            split2(v.z, v.w, hh.y, ll.y);
            uint32_t off = SWX(r, q * 8);
            *(uint2*)(smem + off) = hh;
            *(uint2*)(smem + 16384 + off) = ll;
        }
#pragma unroll
        for (int i = 0; i < 4; i++) {
            int e = i * 256 + t, r = e >> 3, q = e & 7;
            uint32_t off = SWX(r, q * 16);
            *(uint4*)(smem + 32768 + off) = *(const uint4*)&Bh[(size_t)(j0 + r) * 512 + k0 + q * 8];
            *(uint4*)(smem + 49152 + off) = *(const uint4*)&Bl[(size_t)(j0 + r) * 512 + k0 + q * 8];
        }
        GEMM_COMPUTE_CHUNK();
    }
#pragma unroll
    for (int mi = 0; mi < 2; mi++) {
        int row0 = m0 + wm + mi * 16 + g;
#pragma unroll
        for (int ni = 0; ni < 8; ni++) {
            int col = j0 + wn + ni * 8 + tq * 2;
            float2 bbv = *(const float2*)&bo[col];
            float2 o0 = { c[mi][ni][0] + bbv.x, c[mi][ni][1] + bbv.y };
            float2 o1 = { c[mi][ni][2] + bbv.x, c[mi][ni][3] + bbv.y };
            *(float2*)&out[(size_t)row0 * 256 + col] = o0;
            *(float2*)&out[(size_t)(row0 + 8) * 256 + col] = o1;
        }
    }
}

// ================= prep kernels =================
__global__ void zero_kernel() {
    int i = blockIdx.x * blockDim.x + threadIdx.x;
    if (i < BH_ * M_ * CH_) { d_tokx[i] = 0.f; d_tokc[i] = 0.f; }
    if (i < BH_ * M_)       { d_csx[i]  = 0.f; d_csc[i]  = 0.f; }
}

__global__ void prep_wfx(const float* __restrict__ W) {   // W [256][512] -> W^T split
    int j = blockIdx.x, cc = threadIdx.x;
    float wv = W[cc * 512 + j];
    __nv_bfloat16 h = __float2bfloat16(wv);
    d_wfx_h[j * 256 + cc] = h;
    d_wfx_l[j * 256 + cc] = __float2bfloat16(wv - __bfloat162float(h));
}

// Wls^T[j=h*64+m][c] = sum_e Wx[c][h*64+e] * Wslice[e][m]; also bls[j]
__global__ void prep_wls(const float* __restrict__ Wx, const float* __restrict__ Wslice,
                         const float* __restrict__ bx, const float* __restrict__ bslice) {
    extern __shared__ float sm[];
    float* ws = sm;            // [64]
    float* wx = sm + 64;       // [256][68]
    int j = blockIdx.x, h = j >> 6, m = j & 63, t = threadIdx.x;
    if (t < 64) ws[t] = Wslice[t * 64 + m];
    for (int i = t; i < 256 * 16; i += 256) {
        int r = i >> 4, q = i & 15;
        *(float4*)&wx[r * 68 + q * 4] = *(const float4*)&Wx[r * 512 + h * 64 + q * 4];
    }
    __syncthreads();
    float acc = 0.f;
#pragma unroll 8
    for (int e = 0; e < 64; e++) acc += wx[t * 68 + e] * ws[e];
    __nv_bfloat16 hh = __float2bfloat16(acc);
    d_wls_h[j * 256 + t] = hh;
    d_wls_l[j * 256 + t] = __float2bfloat16(acc - __bfloat162float(hh));
    if (t == 0) {
        float bb = bslice[m];
        for (int e = 0; e < 64; e++) bb += bx[h * 64 + e] * ws[e];
        d_bls[j] = bb;
    }
}

__global__ void prep_wot() {   // d_wot[b][512][256] -> [b][256][512] split
    int bc = blockIdx.x;
    int b = bc >> 8, cc = bc & 255, t = threadIdx.x;   // 512 threads
    float wv = d_wot[((size_t)b * 512 + t) * 256 + cc];
    __nv_bfloat16 h = __float2bfloat16(wv);
    d_wot_h[(size_t)bc * 512 + t] = h;
    d_wot_l[(size_t)bc * 512 + t] = __float2bfloat16(wv - __bfloat162float(h));
}

// ================= token aggregation (fp32) =================
__global__ __launch_bounds__(256) void token_kernel(int which_x) {
    float* tok = which_x ? d_tokx : d_tokc;
    float* cs  = which_x ? d_csx  : d_csc;
    const int bh = blockIdx.y;
    const int b = bh >> 3, h = bh & 7;
    const int n0 = blockIdx.x * TK_CHUNK;
    const int t = threadIdx.x;
    __shared__ float sws[16][64];
    __shared__ float fxs[16][64];
    const int lr = t >> 4;
    const int lc = (t & 15) * 4;
    const int gq = t & 15, cq = t >> 4;
    float acc[4][4];
#pragma unroll
    for (int i = 0; i < 4; i++)
#pragma unroll
        for (int j = 0; j < 4; j++) acc[i][j] = 0.f;
    float csacc = 0.f;

    for (int nn = 0; nn < TK_CHUNK; nn += 16) {
        int n = n0 + nn + lr;
        *(float4*)&sws[lr][lc] = *(const float4*)&d_sw[((size_t)bh * N_ + n) * 64 + lc];
        *(float4*)&fxs[lr][lc] = *(const float4*)&d_fx[((size_t)(b * N_ + n)) * 512 + h * 64 + lc];
        __syncthreads();
#pragma unroll
        for (int kk = 0; kk < 16; kk++) {
            float a[4], bb[4];
#pragma unroll
            for (int i = 0; i < 4; i++) a[i] = sws[kk][gq * 4 + i];
#pragma unroll
            for (int j = 0; j < 4; j++) bb[j] = fxs[kk][cq * 4 + j];
#pragma unroll
            for (int i = 0; i < 4; i++)
#pragma unroll
                for (int j = 0; j < 4; j++) acc[i][j] += a[i] * bb[j];
        }
        if (t < 64) {
#pragma unroll
            for (int kk = 0; kk < 16; kk++) csacc += sws[kk][t];
        }
        __syncthreads();
    }
#pragma unroll
    for (int i = 0; i < 4; i++)
#pragma unroll
        for (int j = 0; j < 4; j++)
            atomicAdd(&tok[bh * 4096 + (gq * 4 + i) * 64 + cq * 4 + j], acc[i][j]);
    if (t < 64) atomicAdd(&cs[bh * 64 + t], csacc);
}

// ================= tiny attention + Wo refactor =================
__global__ void attn_kernel(const float* __restrict__ Wq,
                            const float* __restrict__ Wk,
                            const float* __restrict__ Wv) {
    extern __shared__ float sm[];
    float* A  = sm;
    float* Ks = sm + 64 * 65;
    float* Vs = Ks + 64 * 64;
    const int bh = blockIdx.x;
    const int g = threadIdx.x;

    for (int idx = g; idx < 4096; idx += 64) {
        int r = idx >> 6, cc = idx & 63;
        A[r * 65 + cc] = d_tokc[bh * 4096 + idx] / (d_csc[bh * 64 + r] + 1e-5f);
    }
    __syncthreads();
    {
        float ka[64], va[64];
#pragma unroll
        for (int cc = 0; cc < 64; cc++) { ka[cc] = 0.f; va[cc] = 0.f; }
        for (int e = 0; e < 64; e++) {
            float te = A[g * 65 + e];
#pragma unroll
            for (int cc = 0; cc < 64; cc++) {
                ka[cc] += te * Wk[e * 64 + cc];
                va[cc] += te * Wv[e * 64 + cc];
            }
        }
#pragma unroll
        for (int cc = 0; cc < 64; cc++) { Ks[g * 64 + cc] = ka[cc]; Vs[g * 64 + cc] = va[cc]; }
    }
    __syncthreads();
    for (int idx = g; idx < 4096; idx += 64) {
        int r = idx >> 6, cc = idx & 63;
        A[r * 65 + cc] = d_tokx[bh * 4096 + idx] / (d_csx[bh * 64 + r] + 1e-5f);
    }
    __syncthreads();

    float q[64];
#pragma unroll
    for (int cc = 0; cc < 64; cc++) q[cc] = 0.f;
    for (int e = 0; e < 64; e++) {
        float te = A[g * 65 + e];
#pragma unroll
        for (int cc = 0; cc < 64; cc++) q[cc] += te * Wq[e * 64 + cc];
    }
    __syncthreads();
    float* srow = &A[g * 65];
    float mx = -1e30f;
    for (int m = 0; m < 64; m++) {
        float a2 = 0.f;
#pragma unroll
        for (int cc = 0; cc < 64; cc++) a2 += q[cc] * Ks[m * 64 + cc];
        a2 *= 0.125f;
        srow[m] = a2;
        mx = fmaxf(mx, a2);
    }
    float sum = 0.f;
    for (int m = 0; m < 64; m++) { float e = __expf(srow[m] - mx); srow[m] = e; sum += e; }
    float inv = 1.f / sum;
    float o[64];
#pragma unroll
    for (int cc = 0; cc < 64; cc++) o[cc] = 0.f;
    for (int m = 0; m < 64; m++) {
        float p = srow[m] * inv;
#pragma unroll
        for (int cc = 0; cc < 64; cc++) o[cc] += p * Vs[m * 64 + cc];
    }
    float invx = 1.f / (d_csx[bh * 64 + g] + 1e-5f);
#pragma unroll
    for (int cc = 0; cc < 64; cc++) d_outsc[bh * 4096 + g * 64 + cc] = o[cc] * invx;
}

__global__ __launch_bounds__(256) void wot_kernel(const float* __restrict__ Wo) {
    const int bhg = blockIdx.x;
    const int hg = bhg & (H_ * M_ - 1);
    const int h = hg >> 6;
    __shared__ float orow[64];
    const int t = threadIdx.x;
    if (t < 64) orow[t] = d_outsc[bhg * 64 + t];
    __syncthreads();
    float acc = 0.f;
#pragma unroll 8
    for (int cc = 0; cc < 64; cc++) acc += orow[cc] * Wo[(h * 64 + cc) * 256 + t];
    d_wot[(size_t)bhg * 256 + t] = acc;
}

// ================= launcher =================
extern "C" void kernel_launch(void* const* d_in, const int* in_sizes, int n_in,
                              void* d_out, int out_size) {
    const float* x      = (const float*)d_in[0];
    const float* xc     = (const float*)d_in[1];
    const float* Wfx    = (const float*)d_in[2];
    const float* bfx    = (const float*)d_in[3];
    const float* Wx     = (const float*)d_in[4];
    const float* bx     = (const float*)d_in[5];
    const float* Wslice = (const float*)d_in[6];
    const float* bslice = (const float*)d_in[7];
    const float* temp   = (const float*)d_in[8];
    const float* Wq     = (const float*)d_in[9];
    const float* Wk     = (const float*)d_in[10];
    const float* Wv     = (const float*)d_in[11];
    const float* Wo     = (const float*)d_in[12];
    const float* bo     = (const float*)d_in[13];
    float* out = (float*)d_out;

    const int attn_smem = (64 * 65 + 2 * 64 * 64) * (int)sizeof(float);
    const int wls_smem  = (64 + 256 * 68) * (int)sizeof(float);
    cudaFuncSetAttribute(attn_kernel, cudaFuncAttributeMaxDynamicSharedMemorySize, attn_smem);
    cudaFuncSetAttribute(prep_wls,    cudaFuncAttributeMaxDynamicSharedMemorySize, wls_smem);
    cudaFuncSetAttribute(fx_mma,      cudaFuncAttributeMaxDynamicSharedMemorySize, GEMM_SMEM);
    cudaFuncSetAttribute(logit_mma,   cudaFuncAttributeMaxDynamicSharedMemorySize, GEMM_SMEM);
    cudaFuncSetAttribute(final_mma,   cudaFuncAttributeMaxDynamicSharedMemorySize, GEMM_SMEM);

    zero_kernel<<<512, 256>>>();
    prep_wfx<<<512, 256>>>(Wfx);
    prep_wls<<<512, 256, wls_smem>>>(Wx, Wslice, bx, bslice);

    dim3 ggrid(4, ROWS_ / 128);
    dim3 tgrid(N_ / TK_CHUNK, BH_);

    // ---- cross pass ----
    fx_mma<<<ggrid, 256, GEMM_SMEM>>>(xc, bfx);
    logit_mma<<<ggrid, 256, GEMM_SMEM>>>(xc, temp);
    token_kernel<<<tgrid, 256>>>(0);

    // ---- x pass ----
    fx_mma<<<ggrid, 256, GEMM_SMEM>>>(x, bfx);
    logit_mma<<<ggrid, 256, GEMM_SMEM>>>(x, temp);
    token_kernel<<<tgrid, 256>>>(1);

    // ---- tiny attention + epilogue ----
    attn_kernel<<<BH_, 64, attn_smem>>>(Wq, Wk, Wv);
    wot_kernel<<<B_ * H_ * M_, 256>>>(Wo);
    prep_wot<<<B_ * C_, 512>>>();
    final_mma<<<dim3(2, ROWS_ / 128), 256, GEMM_SMEM>>>(bo, out);
}

// round 4
// speedup vs baseline: 2.5398x; 1.2211x over previous
#include <cuda_runtime.h>
#include <cuda_bf16.h>
#include <cstdint>

#define B_ 4
#define N_ 32768
#define C_ 256
#define H_ 8
#define CH_ 64
#define M_ 64
#define INNER_ 512
#define ROWS_ (B_*N_)          // 131072
#define BH_ (B_*H_)            // 32
#define TK_CHUNK 2048

// ================= static scratch =================
__device__ float d_fx[(size_t)ROWS_ * 512];            // x@Wfx+bfx (fp32, for token_kernel)
__device__ float d_sw[(size_t)BH_ * N_ * M_];          // softmax weights fp32 (token_kernel)
__device__ __nv_bfloat16 d_sw_h[(size_t)BH_ * N_ * M_];// sw split (final_mma)
__device__ __nv_bfloat16 d_sw_l[(size_t)BH_ * N_ * M_];
__device__ __nv_bfloat16 d_xs_h[(size_t)ROWS_ * 256];  // current input split
__device__ __nv_bfloat16 d_xs_l[(size_t)ROWS_ * 256];
__device__ float d_tokx[BH_ * M_ * CH_];
__device__ float d_tokc[BH_ * M_ * CH_];
__device__ float d_csx[BH_ * M_];
__device__ float d_csc[BH_ * M_];
__device__ float d_outsc[BH_ * M_ * CH_];
__device__ float d_wot[B_ * INNER_ * C_];
__device__ float d_bls[INNER_];
__device__ __nv_bfloat16 d_wfx_h[INNER_ * C_];         // Wfx^T split  [512][256]
__device__ __nv_bfloat16 d_wfx_l[INNER_ * C_];
__device__ __nv_bfloat16 d_wls_h[INNER_ * C_];         // (Wx@Wslice)^T split [512][256]
__device__ __nv_bfloat16 d_wls_l[INNER_ * C_];
__device__ __nv_bfloat16 d_wot_h[B_ * C_ * INNER_];    // wot^T split [b][256][512]
__device__ __nv_bfloat16 d_wot_l[B_ * C_ * INNER_];

// ================= helpers =================
__device__ __forceinline__ uint32_t smem_u32(const void* p) {
    uint32_t a;
    asm("{ .reg .u64 t; cvta.to.shared.u64 t, %1; cvt.u32.u64 %0, t; }" : "=r"(a) : "l"(p));
    return a;
}
__device__ __forceinline__ void ldsm4(uint32_t* r, uint32_t addr) {
    asm volatile("ldmatrix.sync.aligned.m8n8.x4.shared.b16 {%0,%1,%2,%3}, [%4];"
                 : "=r"(r[0]), "=r"(r[1]), "=r"(r[2]), "=r"(r[3]) : "r"(addr));
}
__device__ __forceinline__ void mma16816(float* c, const uint32_t* a, const uint32_t* b) {
    asm volatile("mma.sync.aligned.m16n8k16.row.col.f32.bf16.bf16.f32 "
                 "{%0,%1,%2,%3}, {%4,%5,%6,%7}, {%8,%9}, {%0,%1,%2,%3};"
                 : "+f"(c[0]), "+f"(c[1]), "+f"(c[2]), "+f"(c[3])
                 : "r"(a[0]), "r"(a[1]), "r"(a[2]), "r"(a[3]), "r"(b[0]), "r"(b[1]));
}
__device__ __forceinline__ void split2(float x, float y, uint32_t& hi, uint32_t& lo) {
    __nv_bfloat16 hx = __float2bfloat16(x), hy = __float2bfloat16(y);
    float rx = x - __bfloat162float(hx), ry = y - __bfloat162float(hy);
    __nv_bfloat16 lx = __float2bfloat16(rx), ly = __float2bfloat16(ry);
    hi = (uint32_t)__bfloat16_as_ushort(hx) | ((uint32_t)__bfloat16_as_ushort(hy) << 16);
    lo = (uint32_t)__bfloat16_as_ushort(lx) | ((uint32_t)__bfloat16_as_ushort(ly) << 16);
}
__device__ __forceinline__ void cpa16(uint32_t dst, const void* src) {
    asm volatile("cp.async.cg.shared.global [%0], [%1], 16;" :: "r"(dst), "l"(src));
}
#define CP_COMMIT() asm volatile("cp.async.commit_group;" ::: "memory")
#define CP_WAIT1()  asm volatile("cp.async.wait_group 1;" ::: "memory")

// smem: 2 stages x 64KB:  [A_hi 16K][A_lo 16K][B_hi 16K][B_lo 16K]
#define STAGE_BYTES 65536
#define GEMM_SMEM  131072
#define SWX(r, byte) ((uint32_t)((r) * 128 + ((byte) ^ (((r) & 7) << 4))))

// ===================================================================
// warp layout: 8 warps; warp_m = w&3 (32 rows each), warp_n = w>>2 (64 cols each)
// ===================================================================
#define GEMM_PROLOG() \
    extern __shared__ char smem[]; \
    const uint32_t sb = smem_u32(smem); \
    const int t = threadIdx.x; \
    const int w = t >> 5, lane = t & 31; \
    const int wm = (w & 3) * 32, wn = (w >> 2) * 64; \
    const int g = lane >> 2, tq = lane & 3; \
    const int ar_ = lane & 15, akh_ = lane >> 4; \
    const int qd_ = lane >> 3, bl8_ = lane & 7; \
    uint32_t abase[2], axr[2], bbase[4], bxr[4]; \
    _Pragma("unroll") for (int mi = 0; mi < 2; mi++) { \
        int row = wm + mi * 16 + ar_; \
        abase[mi] = row * 128; axr[mi] = (row & 7) << 4; \
    } \
    _Pragma("unroll") for (int nb = 0; nb < 4; nb++) { \
        int row = wn + nb * 16 + (qd_ >> 1) * 8 + bl8_; \
        bbase[nb] = row * 128; bxr[nb] = (row & 7) << 4; \
    } \
    const uint32_t bk16_ = (qd_ & 1) * 16; \
    const uint32_t ak16_ = akh_ * 16; \
    float c[2][8][4]; \
    _Pragma("unroll") for (int mi = 0; mi < 2; mi++) \
    _Pragma("unroll") for (int ni = 0; ni < 8; ni++) \
    _Pragma("unroll") for (int q = 0; q < 4; q++) c[mi][ni][q] = 0.f;

#define GEMM_COMPUTE_CHUNK(soff) \
    _Pragma("unroll") for (int ks = 0; ks < 4; ks++) { \
        uint32_t ah[2][4], al[2][4], bh[8][2], bl[8][2]; \
        const uint32_t ka = ks * 32 + ak16_; \
        const uint32_t kb = ks * 32 + bk16_; \
        _Pragma("unroll") for (int mi = 0; mi < 2; mi++) { \
            uint32_t off = (soff) + abase[mi] + (ka ^ axr[mi]); \
            ldsm4(ah[mi], sb + off); \
            ldsm4(al[mi], sb + 16384 + off); \
        } \
        _Pragma("unroll") for (int nb = 0; nb < 4; nb++) { \
            uint32_t off = (soff) + bbase[nb] + (kb ^ bxr[nb]); \
            uint32_t rh[4], rl[4]; \
            ldsm4(rh, sb + 32768 + off); \
            ldsm4(rl, sb + 49152 + off); \
            bh[nb*2][0] = rh[0]; bh[nb*2][1] = rh[1]; \
            bh[nb*2+1][0] = rh[2]; bh[nb*2+1][1] = rh[3]; \
            bl[nb*2][0] = rl[0]; bl[nb*2][1] = rl[1]; \
            bl[nb*2+1][0] = rl[2]; bl[nb*2+1][1] = rl[3]; \
        } \
        _Pragma("unroll") for (int mi = 0; mi < 2; mi++) \
        _Pragma("unroll") for (int ni = 0; ni < 8; ni++) { \
            mma16816(c[mi][ni], ah[mi], bh[ni]); \
            mma16816(c[mi][ni], ah[mi], bl[ni]); \
            mma16816(c[mi][ni], al[mi], bh[ni]); \
        } \
    }

// issue one 64-wide k-chunk: A from (Ahp,Alp) stride 256, B from (Bhp,Blp) stride 256
#define ISSUE_256(Ahp, Alp, Bhp, Blp, m0, j0, k0, s) \
    { \
        uint32_t so = sb + (uint32_t)(s) * STAGE_BYTES; \
        _Pragma("unroll") for (int i = 0; i < 4; i++) { \
            int e = i * 256 + t, r = e >> 3, q = e & 7; \
            uint32_t off = SWX(r, q * 16); \
            cpa16(so + off,         &(Ahp)[(size_t)((m0) + r) * 256 + (k0) + q * 8]); \
            cpa16(so + 16384 + off, &(Alp)[(size_t)((m0) + r) * 256 + (k0) + q * 8]); \
            cpa16(so + 32768 + off, &(Bhp)[(size_t)((j0) + r) * 256 + (k0) + q * 8]); \
            cpa16(so + 49152 + off, &(Blp)[(size_t)((j0) + r) * 256 + (k0) + q * 8]); \
        } \
    }

#define PIPELINE(NC, ISSUE_CH) \
    ISSUE_CH(0, 0); \
    CP_COMMIT(); \
    for (int ch = 0; ch < (NC); ch++) { \
        if (ch + 1 < (NC)) { ISSUE_CH(ch + 1, (ch + 1) & 1); } \
        CP_COMMIT(); \
        CP_WAIT1(); \
        __syncthreads(); \
        GEMM_COMPUTE_CHUNK((uint32_t)(ch & 1) * STAGE_BYTES); \
        __syncthreads(); \
    }

// ================= GEMM 1: d_fx = X @ Wfx + bfx =================
__global__ __launch_bounds__(256) void fx_mma(const float* __restrict__ bias) {
    GEMM_PROLOG();
    const int m0 = blockIdx.y * 128;
    const int j0 = blockIdx.x * 128;
#define FX_ISSUE(ch, s) ISSUE_256(d_xs_h, d_xs_l, d_wfx_h, d_wfx_l, m0, j0, (ch) * 64, s)
    PIPELINE(4, FX_ISSUE);
#undef FX_ISSUE
#pragma unroll
    for (int mi = 0; mi < 2; mi++) {
        int row0 = m0 + wm + mi * 16 + g;
#pragma unroll
        for (int ni = 0; ni < 8; ni++) {
            int col = j0 + wn + ni * 8 + tq * 2;
            float2 bb = *(const float2*)&bias[col];
            float2 o0 = { c[mi][ni][0] + bb.x, c[mi][ni][1] + bb.y };
            float2 o1 = { c[mi][ni][2] + bb.x, c[mi][ni][3] + bb.y };
            *(float2*)&d_fx[(size_t)row0 * 512 + col] = o0;
            *(float2*)&d_fx[(size_t)(row0 + 8) * 512 + col] = o1;
        }
    }
}

// ================= GEMM 2: logits, fused softmax -> d_sw (fp32 + bf16 split) =================
__global__ __launch_bounds__(256) void logit_mma(const float* __restrict__ temperature) {
    GEMM_PROLOG();
    const int m0 = blockIdx.y * 128;
    const int j0 = blockIdx.x * 128;
#define LG_ISSUE(ch, s) ISSUE_256(d_xs_h, d_xs_l, d_wls_h, d_wls_l, m0, j0, (ch) * 64, s)
    PIPELINE(4, LG_ISSUE);
#undef LG_ISSUE
    const int h = (j0 >> 6) + (w >> 2);
    float tp = temperature[h];
    tp = fminf(fmaxf(tp, 0.1f), 5.0f);
    const float invt = 1.f / tp;
    float2 blv[8];
#pragma unroll
    for (int ni = 0; ni < 8; ni++)
        blv[ni] = *(const float2*)&d_bls[j0 + wn + ni * 8 + tq * 2];
#pragma unroll
    for (int mi = 0; mi < 2; mi++)
#pragma unroll
        for (int ni = 0; ni < 8; ni++) {
            c[mi][ni][0] = (c[mi][ni][0] + blv[ni].x) * invt;
            c[mi][ni][1] = (c[mi][ni][1] + blv[ni].y) * invt;
            c[mi][ni][2] = (c[mi][ni][2] + blv[ni].x) * invt;
            c[mi][ni][3] = (c[mi][ni][3] + blv[ni].y) * invt;
        }
#pragma unroll
    for (int mi = 0; mi < 2; mi++)
#pragma unroll
        for (int half = 0; half < 2; half++) {
            const int ci = half * 2;
            float mx = -1e30f;
#pragma unroll
            for (int ni = 0; ni < 8; ni++)
                mx = fmaxf(mx, fmaxf(c[mi][ni][ci], c[mi][ni][ci + 1]));
            mx = fmaxf(mx, __shfl_xor_sync(0xffffffffu, mx, 1));
            mx = fmaxf(mx, __shfl_xor_sync(0xffffffffu, mx, 2));
            float s = 0.f;
#pragma unroll
            for (int ni = 0; ni < 8; ni++) {
                float e0 = __expf(c[mi][ni][ci] - mx);
                float e1 = __expf(c[mi][ni][ci + 1] - mx);
                c[mi][ni][ci] = e0; c[mi][ni][ci + 1] = e1;
                s += e0 + e1;
            }
            s += __shfl_xor_sync(0xffffffffu, s, 1);
            s += __shfl_xor_sync(0xffffffffu, s, 2);
            float inv = 1.f / s;
            int row = m0 + wm + mi * 16 + half * 8 + g;
            int b = row >> 15, n = row & (N_ - 1);
            size_t base = ((size_t)(b * H_ + h) * N_ + n) * 64;
#pragma unroll
            for (int ni = 0; ni < 8; ni++) {
                float2 o = { c[mi][ni][ci] * inv, c[mi][ni][ci + 1] * inv };
                size_t idx = base + ni * 8 + tq * 2;
                *(float2*)&d_sw[idx] = o;
                uint32_t hh, ll;
                split2(o.x, o.y, hh, ll);
                *(uint32_t*)&d_sw_h[idx] = hh;
                *(uint32_t*)&d_sw_l[idx] = ll;
            }
        }
}

// ================= GEMM 3: out[b] = sw[b] (N x 512) @ wot[b] (512 x 256) + bo =================
__global__ __launch_bounds__(256) void final_mma(const float* __restrict__ bo,
                                                 float* __restrict__ out) {
    GEMM_PROLOG();
    const int m0 = blockIdx.y * 128;
    const int j0 = blockIdx.x * 128;
    const int bb_ = m0 >> 15;
    const int n0 = m0 & (N_ - 1);
#define FN_ISSUE(ch, s) \
    { \
        uint32_t so = sb + (uint32_t)(s) * STAGE_BYTES; \
        const int k0 = (ch) * 64; \
        _Pragma("unroll") for (int i = 0; i < 4; i++) { \
            int e = i * 256 + t, r = e >> 3, q = e & 7; \
            uint32_t off = SWX(r, q * 16); \
            size_t aidx = ((size_t)(bb_ * H_ + (ch)) * N_ + n0 + r) * 64 + q * 8; \
            cpa16(so + off,         &d_sw_h[aidx]); \
            cpa16(so + 16384 + off, &d_sw_l[aidx]); \
            size_t bidx = ((size_t)bb_ * 256 + j0 + r) * 512 + k0 + q * 8; \
            cpa16(so + 32768 + off, &d_wot_h[bidx]); \
            cpa16(so + 49152 + off, &d_wot_l[bidx]); \
        } \
    }
    PIPELINE(8, FN_ISSUE);
#undef FN_ISSUE
#pragma unroll
    for (int mi = 0; mi < 2; mi++) {
        int row0 = m0 + wm + mi * 16 + g;
#pragma unroll
        for (int ni = 0; ni < 8; ni++) {
            int col = j0 + wn + ni * 8 + tq * 2;
            float2 bbv = *(const float2*)&bo[col];
            float2 o0 = { c[mi][ni][0] + bbv.x, c[mi][ni][1] + bbv.y };
            float2 o1 = { c[mi][ni][2] + bbv.x, c[mi][ni][3] + bbv.y };
            *(float2*)&out[(size_t)row0 * 256 + col] = o0;
            *(float2*)&out[(size_t)(row0 + 8) * 256 + col] = o1;
        }
    }
}

// ================= prep kernels =================
__global__ void presplit_x(const float* __restrict__ X) {
    size_t i = (size_t)blockIdx.x * 256 + threadIdx.x;   // indexes float4 groups
    float4 v = ((const float4*)X)[i];
    uint2 hh, ll;
    split2(v.x, v.y, hh.x, ll.x);
    split2(v.z, v.w, hh.y, ll.y);
    ((uint2*)d_xs_h)[i] = hh;
    ((uint2*)d_xs_l)[i] = ll;
}

__global__ void zero_kernel() {
    int i = blockIdx.x * blockDim.x + threadIdx.x;
    if (i < BH_ * M_ * CH_) { d_tokx[i] = 0.f; d_tokc[i] = 0.f; }
    if (i < BH_ * M_)       { d_csx[i]  = 0.f; d_csc[i]  = 0.f; }
}

__global__ void prep_wfx(const float* __restrict__ W) {   // W [256][512] -> W^T split
    int j = blockIdx.x, cc = threadIdx.x;
    float wv = W[cc * 512 + j];
    __nv_bfloat16 h = __float2bfloat16(wv);
    d_wfx_h[j * 256 + cc] = h;
    d_wfx_l[j * 256 + cc] = __float2bfloat16(wv - __bfloat162float(h));
}

// Wls^T[j=h*64+m][c] = sum_e Wx[c][h*64+e] * Wslice[e][m]; also bls[j]
__global__ void prep_wls(const float* __restrict__ Wx, const float* __restrict__ Wslice,
                         const float* __restrict__ bx, const float* __restrict__ bslice) {
    extern __shared__ float sm[];
    float* ws = sm;            // [64]
    float* wx = sm + 64;       // [256][68]
    int j = blockIdx.x, h = j >> 6, m = j & 63, t = threadIdx.x;
    if (t < 64) ws[t] = Wslice[t * 64 + m];
    for (int i = t; i < 256 * 16; i += 256) {
        int r = i >> 4, q = i & 15;
        *(float4*)&wx[r * 68 + q * 4] = *(const float4*)&Wx[r * 512 + h * 64 + q * 4];
    }
    __syncthreads();
    float acc = 0.f;
#pragma unroll 8
    for (int e = 0; e < 64; e++) acc += wx[t * 68 + e] * ws[e];
    __nv_bfloat16 hh = __float2bfloat16(acc);
    d_wls_h[j * 256 + t] = hh;
    d_wls_l[j * 256 + t] = __float2bfloat16(acc - __bfloat162float(hh));
    if (t == 0) {
        float bb = bslice[m];
        for (int e = 0; e < 64; e++) bb += bx[h * 64 + e] * ws[e];
        d_bls[j] = bb;
    }
}

__global__ void prep_wot() {   // d_wot[b][512][256] -> [b][256][512] split
    int bc = blockIdx.x;
    int b = bc >> 8, cc = bc & 255, t = threadIdx.x;   // 512 threads
    float wv = d_wot[((size_t)b * 512 + t) * 256 + cc];
    __nv_bfloat16 h = __float2bfloat16(wv);
    d_wot_h[(size_t)bc * 512 + t] = h;
    d_wot_l[(size_t)bc * 512 + t] = __float2bfloat16(wv - __bfloat162float(h));
}

// ================= token aggregation (fp32) =================
__global__ __launch_bounds__(256) void token_kernel(int which_x) {
    float* tok = which_x ? d_tokx : d_tokc;
    float* cs  = which_x ? d_csx  : d_csc;
    const int bh = blockIdx.y;
    const int b = bh >> 3, h = bh & 7;
    const int n0 = blockIdx.x * TK_CHUNK;
    const int t = threadIdx.x;
    __shared__ float sws[16][64];
    __shared__ float fxs[16][64];
    const int lr = t >> 4;
    const int lc = (t & 15) * 4;
    const int gq = t & 15, cq = t >> 4;
    float acc[4][4];
#pragma unroll
    for (int i = 0; i < 4; i++)
#pragma unroll
        for (int j = 0; j < 4; j++) acc[i][j] = 0.f;
    float csacc = 0.f;

    for (int nn = 0; nn < TK_CHUNK; nn += 16) {
        int n = n0 + nn + lr;
        *(float4*)&sws[lr][lc] = *(const float4*)&d_sw[((size_t)bh * N_ + n) * 64 + lc];
        *(float4*)&fxs[lr][lc] = *(const float4*)&d_fx[((size_t)(b * N_ + n)) * 512 + h * 64 + lc];
        __syncthreads();
#pragma unroll
        for (int kk = 0; kk < 16; kk++) {
            float a[4], bb[4];
#pragma unroll
            for (int i = 0; i < 4; i++) a[i] = sws[kk][gq * 4 + i];
#pragma unroll
            for (int j = 0; j < 4; j++) bb[j] = fxs[kk][cq * 4 + j];
#pragma unroll
            for (int i = 0; i < 4; i++)
#pragma unroll
                for (int j = 0; j < 4; j++) acc[i][j] += a[i] * bb[j];
        }
        if (t < 64) {
#pragma unroll
            for (int kk = 0; kk < 16; kk++) csacc += sws[kk][t];
        }
        __syncthreads();
    }
#pragma unroll
    for (int i = 0; i < 4; i++)
#pragma unroll
        for (int j = 0; j < 4; j++)
            atomicAdd(&tok[bh * 4096 + (gq * 4 + i) * 64 + cq * 4 + j], acc[i][j]);
    if (t < 64) atomicAdd(&cs[bh * 64 + t], csacc);
}

// ================= tiny attention + Wo refactor =================
__global__ void attn_kernel(const float* __restrict__ Wq,
                            const float* __restrict__ Wk,
                            const float* __restrict__ Wv) {
    extern __shared__ float sm[];
    float* A  = sm;
    float* Ks = sm + 64 * 65;
    float* Vs = Ks + 64 * 64;
    const int bh = blockIdx.x;
    const int g = threadIdx.x;

    for (int idx = g; idx < 4096; idx += 64) {
        int r = idx >> 6, cc = idx & 63;
        A[r * 65 + cc] = d_tokc[bh * 4096 + idx] / (d_csc[bh * 64 + r] + 1e-5f);
    }
    __syncthreads();
    {
        float ka[64], va[64];
#pragma unroll
        for (int cc = 0; cc < 64; cc++) { ka[cc] = 0.f; va[cc] = 0.f; }
        for (int e = 0; e < 64; e++) {
            float te = A[g * 65 + e];
#pragma unroll
            for (int cc = 0; cc < 64; cc++) {
                ka[cc] += te * Wk[e * 64 + cc];
                va[cc] += te * Wv[e * 64 + cc];
            }
        }
#pragma unroll
        for (int cc = 0; cc < 64; cc++) { Ks[g * 64 + cc] = ka[cc]; Vs[g * 64 + cc] = va[cc]; }
    }
    __syncthreads();
    for (int idx = g; idx < 4096; idx += 64) {
        int r = idx >> 6, cc = idx & 63;
        A[r * 65 + cc] = d_tokx[bh * 4096 + idx] / (d_csx[bh * 64 + r] + 1e-5f);
    }
    __syncthreads();

    float q[64];
#pragma unroll
    for (int cc = 0; cc < 64; cc++) q[cc] = 0.f;
    for (int e = 0; e < 64; e++) {
        float te = A[g * 65 + e];
#pragma unroll
        for (int cc = 0; cc < 64; cc++) q[cc] += te * Wq[e * 64 + cc];
    }
    __syncthreads();
    float* srow = &A[g * 65];
    float mx = -1e30f;
    for (int m = 0; m < 64; m++) {
        float a2 = 0.f;
#pragma unroll
        for (int cc = 0; cc < 64; cc++) a2 += q[cc] * Ks[m * 64 + cc];
        a2 *= 0.125f;
        srow[m] = a2;
        mx = fmaxf(mx, a2);
    }
    float sum = 0.f;
    for (int m = 0; m < 64; m++) { float e = __expf(srow[m] - mx); srow[m] = e; sum += e; }
    float inv = 1.f / sum;
    float o[64];
#pragma unroll
    for (int cc = 0; cc < 64; cc++) o[cc] = 0.f;
    for (int m = 0; m < 64; m++) {
        float p = srow[m] * inv;
#pragma unroll
        for (int cc = 0; cc < 64; cc++) o[cc] += p * Vs[m * 64 + cc];
    }
    float invx = 1.f / (d_csx[bh * 64 + g] + 1e-5f);
#pragma unroll
    for (int cc = 0; cc < 64; cc++) d_outsc[bh * 4096 + g * 64 + cc] = o[cc] * invx;
}

__global__ __launch_bounds__(256) void wot_kernel(const float* __restrict__ Wo) {
    const int bhg = blockIdx.x;
    const int hg = bhg & (H_ * M_ - 1);
    const int h = hg >> 6;
    __shared__ float orow[64];
    const int t = threadIdx.x;
    if (t < 64) orow[t] = d_outsc[bhg * 64 + t];
    __syncthreads();
    float acc = 0.f;
#pragma unroll 8
    for (int cc = 0; cc < 64; cc++) acc += orow[cc] * Wo[(h * 64 + cc) * 256 + t];
    d_wot[(size_t)bhg * 256 + t] = acc;
}

// ================= launcher =================
extern "C" void kernel_launch(void* const* d_in, const int* in_sizes, int n_in,
                              void* d_out, int out_size) {
    const float* x      = (const float*)d_in[0];
    const float* xc     = (const float*)d_in[1];
    const float* Wfx    = (const float*)d_in[2];
    const float* bfx    = (const float*)d_in[3];
    const float* Wx     = (const float*)d_in[4];
    const float* bx     = (const float*)d_in[5];
    const float* Wslice = (const float*)d_in[6];
    const float* bslice = (const float*)d_in[7];
    const float* temp   = (const float*)d_in[8];
    const float* Wq     = (const float*)d_in[9];
    const float* Wk     = (const float*)d_in[10];
    const float* Wv     = (const float*)d_in[11];
    const float* Wo     = (const float*)d_in[12];
    const float* bo     = (const float*)d_in[13];
    float* out = (float*)d_out;

    const int attn_smem = (64 * 65 + 2 * 64 * 64) * (int)sizeof(float);
    const int wls_smem  = (64 + 256 * 68) * (int)sizeof(float);
    cudaFuncSetAttribute(attn_kernel, cudaFuncAttributeMaxDynamicSharedMemorySize, attn_smem);
    cudaFuncSetAttribute(prep_wls,    cudaFuncAttributeMaxDynamicSharedMemorySize, wls_smem);
    cudaFuncSetAttribute(fx_mma,      cudaFuncAttributeMaxDynamicSharedMemorySize, GEMM_SMEM);
    cudaFuncSetAttribute(logit_mma,   cudaFuncAttributeMaxDynamicSharedMemorySize, GEMM_SMEM);
    cudaFuncSetAttribute(final_mma,   cudaFuncAttributeMaxDynamicSharedMemorySize, GEMM_SMEM);

    zero_kernel<<<512, 256>>>();
    prep_wfx<<<512, 256>>>(Wfx);
    prep_wls<<<512, 256, wls_smem>>>(Wx, Wslice, bx, bslice);

    dim3 ggrid(4, ROWS_ / 128);
    dim3 tgrid(N_ / TK_CHUNK, BH_);
    const int ps_blocks = (int)((size_t)ROWS_ * 256 / 4 / 256);

    // ---- cross pass ----
    presplit_x<<<ps_blocks, 256>>>(xc);
    fx_mma<<<ggrid, 256, GEMM_SMEM>>>(bfx);
    logit_mma<<<ggrid, 256, GEMM_SMEM>>>(temp);
    token_kernel<<<tgrid, 256>>>(0);

    // ---- x pass ----
    presplit_x<<<ps_blocks, 256>>>(x);
    fx_mma<<<ggrid, 256, GEMM_SMEM>>>(bfx);
    logit_mma<<<ggrid, 256, GEMM_SMEM>>>(temp);
    token_kernel<<<tgrid, 256>>>(1);

    // ---- tiny attention + epilogue ----
    attn_kernel<<<BH_, 64, attn_smem>>>(Wq, Wk, Wv);
    wot_kernel<<<B_ * H_ * M_, 256>>>(Wo);
    prep_wot<<<B_ * C_, 512>>>();
    final_mma<<<dim3(2, ROWS_ / 128), 256, GEMM_SMEM>>>(bo, out);
}

// round 5
// speedup vs baseline: 2.9605x; 1.1657x over previous
#include <cuda_runtime.h>
#include <cuda_bf16.h>
#include <cstdint>

#define B_ 4
#define N_ 32768
#define C_ 256
#define H_ 8
#define CH_ 64
#define M_ 64
#define INNER_ 512
#define ROWS_ (B_*N_)          // 131072
#define BH_ (B_*H_)            // 32

// ================= static scratch =================
__device__ __nv_bfloat16 d_fx_h[(size_t)ROWS_ * 512]; // fx split (token_mma)
__device__ __nv_bfloat16 d_fx_l[(size_t)ROWS_ * 512];
__device__ __nv_bfloat16 d_sw_h[(size_t)BH_ * N_ * M_];// sw split (token_mma + final_mma)
__device__ __nv_bfloat16 d_sw_l[(size_t)BH_ * N_ * M_];
__device__ __nv_bfloat16 d_xs_h[(size_t)ROWS_ * 256];  // current input split
__device__ __nv_bfloat16 d_xs_l[(size_t)ROWS_ * 256];
__device__ float d_tokx[BH_ * M_ * CH_];
__device__ float d_tokc[BH_ * M_ * CH_];
__device__ float d_csx[BH_ * M_];
__device__ float d_csc[BH_ * M_];
__device__ float d_outsc[BH_ * M_ * CH_];
__device__ float d_wot[B_ * INNER_ * C_];
__device__ float d_bls[INNER_];
__device__ __nv_bfloat16 d_wfx_h[INNER_ * C_];         // Wfx^T split  [512][256]
__device__ __nv_bfloat16 d_wfx_l[INNER_ * C_];
__device__ __nv_bfloat16 d_wls_h[INNER_ * C_];         // (Wx@Wslice)^T split [512][256]
__device__ __nv_bfloat16 d_wls_l[INNER_ * C_];
__device__ __nv_bfloat16 d_wot_h[B_ * C_ * INNER_];    // wot^T split [b][256][512]
__device__ __nv_bfloat16 d_wot_l[B_ * C_ * INNER_];

// ================= helpers =================
__device__ __forceinline__ uint32_t smem_u32(const void* p) {
    uint32_t a;
    asm("{ .reg .u64 t; cvta.to.shared.u64 t, %1; cvt.u32.u64 %0, t; }" : "=r"(a) : "l"(p));
    return a;
}
__device__ __forceinline__ void ldsm4(uint32_t* r, uint32_t addr) {
    asm volatile("ldmatrix.sync.aligned.m8n8.x4.shared.b16 {%0,%1,%2,%3}, [%4];"
                 : "=r"(r[0]), "=r"(r[1]), "=r"(r[2]), "=r"(r[3]) : "r"(addr));
}
__device__ __forceinline__ void ldsm4t(uint32_t* r, uint32_t addr) {
    asm volatile("ldmatrix.sync.aligned.m8n8.x4.trans.shared.b16 {%0,%1,%2,%3}, [%4];"
                 : "=r"(r[0]), "=r"(r[1]), "=r"(r[2]), "=r"(r[3]) : "r"(addr));
}
__device__ __forceinline__ void mma16816(float* c, const uint32_t* a, const uint32_t* b) {
    asm volatile("mma.sync.aligned.m16n8k16.row.col.f32.bf16.bf16.f32 "
                 "{%0,%1,%2,%3}, {%4,%5,%6,%7}, {%8,%9}, {%0,%1,%2,%3};"
                 : "+f"(c[0]), "+f"(c[1]), "+f"(c[2]), "+f"(c[3])
                 : "r"(a[0]), "r"(a[1]), "r"(a[2]), "r"(a[3]), "r"(b[0]), "r"(b[1]));
}
__device__ __forceinline__ void split2(float x, float y, uint32_t& hi, uint32_t& lo) {
    __nv_bfloat16 hx = __float2bfloat16(x), hy = __float2bfloat16(y);
    float rx = x - __bfloat162float(hx), ry = y - __bfloat162float(hy);
    __nv_bfloat16 lx = __float2bfloat16(rx), ly = __float2bfloat16(ry);
    hi = (uint32_t)__bfloat16_as_ushort(hx) | ((uint32_t)__bfloat16_as_ushort(hy) << 16);
    lo = (uint32_t)__bfloat16_as_ushort(lx) | ((uint32_t)__bfloat16_as_ushort(ly) << 16);
}
__device__ __forceinline__ void cpa16(uint32_t dst, const void* src) {
    asm volatile("cp.async.cg.shared.global [%0], [%1], 16;" :: "r"(dst), "l"(src));
}
#define CP_COMMIT() asm volatile("cp.async.commit_group;" ::: "memory")
#define CP_WAIT1()  asm volatile("cp.async.wait_group 1;" ::: "memory")

// smem: 2 stages x 64KB:  [A_hi 16K][A_lo 16K][B_hi 16K][B_lo 16K]
#define STAGE_BYTES 65536
#define GEMM_SMEM  131072
#define SWX(r, byte) ((uint32_t)((r) * 128 + ((byte) ^ (((r) & 7) << 4))))

// ===================================================================
// warp layout: 8 warps; warp_m = w&3 (32 rows each), warp_n = w>>2 (64 cols each)
// ===================================================================
#define GEMM_PROLOG() \
    extern __shared__ char smem[]; \
    const uint32_t sb = smem_u32(smem); \
    const int t = threadIdx.x; \
    const int w = t >> 5, lane = t & 31; \
    const int wm = (w & 3) * 32, wn = (w >> 2) * 64; \
    const int g = lane >> 2, tq = lane & 3; \
    const int ar_ = lane & 15, akh_ = lane >> 4; \
    const int qd_ = lane >> 3, bl8_ = lane & 7; \
    uint32_t abase[2], axr[2], bbase[4], bxr[4]; \
    _Pragma("unroll") for (int mi = 0; mi < 2; mi++) { \
        int row = wm + mi * 16 + ar_; \
        abase[mi] = row * 128; axr[mi] = (row & 7) << 4; \
    } \
    _Pragma("unroll") for (int nb = 0; nb < 4; nb++) { \
        int row = wn + nb * 16 + (qd_ >> 1) * 8 + bl8_; \
        bbase[nb] = row * 128; bxr[nb] = (row & 7) << 4; \
    } \
    const uint32_t bk16_ = (qd_ & 1) * 16; \
    const uint32_t ak16_ = akh_ * 16; \
    float c[2][8][4]; \
    _Pragma("unroll") for (int mi = 0; mi < 2; mi++) \
    _Pragma("unroll") for (int ni = 0; ni < 8; ni++) \
    _Pragma("unroll") for (int q = 0; q < 4; q++) c[mi][ni][q] = 0.f;

#define GEMM_COMPUTE_CHUNK(soff) \
    _Pragma("unroll") for (int ks = 0; ks < 4; ks++) { \
        uint32_t ah[2][4], al[2][4], bh[8][2], bl[8][2]; \
        const uint32_t ka = ks * 32 + ak16_; \
        const uint32_t kb = ks * 32 + bk16_; \
        _Pragma("unroll") for (int mi = 0; mi < 2; mi++) { \
            uint32_t off = (soff) + abase[mi] + (ka ^ axr[mi]); \
            ldsm4(ah[mi], sb + off); \
            ldsm4(al[mi], sb + 16384 + off); \
        } \
        _Pragma("unroll") for (int nb = 0; nb < 4; nb++) { \
            uint32_t off = (soff) + bbase[nb] + (kb ^ bxr[nb]); \
            uint32_t rh[4], rl[4]; \
            ldsm4(rh, sb + 32768 + off); \
            ldsm4(rl, sb + 49152 + off); \
            bh[nb*2][0] = rh[0]; bh[nb*2][1] = rh[1]; \
            bh[nb*2+1][0] = rh[2]; bh[nb*2+1][1] = rh[3]; \
            bl[nb*2][0] = rl[0]; bl[nb*2][1] = rl[1]; \
            bl[nb*2+1][0] = rl[2]; bl[nb*2+1][1] = rl[3]; \
        } \
        _Pragma("unroll") for (int mi = 0; mi < 2; mi++) \
        _Pragma("unroll") for (int ni = 0; ni < 8; ni++) { \
            mma16816(c[mi][ni], ah[mi], bh[ni]); \
            mma16816(c[mi][ni], ah[mi], bl[ni]); \
            mma16816(c[mi][ni], al[mi], bh[ni]); \
        } \
    }

// issue one 64-wide k-chunk: A from (Ahp,Alp) stride 256, B from (Bhp,Blp) stride 256
#define ISSUE_256(Ahp, Alp, Bhp, Blp, m0, j0, k0, s) \
    { \
        uint32_t so = sb + (uint32_t)(s) * STAGE_BYTES; \
        _Pragma("unroll") for (int i = 0; i < 4; i++) { \
            int e = i * 256 + t, r = e >> 3, q = e & 7; \
            uint32_t off = SWX(r, q * 16); \
            cpa16(so + off,         &(Ahp)[(size_t)((m0) + r) * 256 + (k0) + q * 8]); \
            cpa16(so + 16384 + off, &(Alp)[(size_t)((m0) + r) * 256 + (k0) + q * 8]); \
            cpa16(so + 32768 + off, &(Bhp)[(size_t)((j0) + r) * 256 + (k0) + q * 8]); \
            cpa16(so + 49152 + off, &(Blp)[(size_t)((j0) + r) * 256 + (k0) + q * 8]); \
        } \
    }

#define PIPELINE(NC, ISSUE_CH) \
    ISSUE_CH(0, 0); \
    CP_COMMIT(); \
    for (int ch = 0; ch < (NC); ch++) { \
        if (ch + 1 < (NC)) { ISSUE_CH(ch + 1, (ch + 1) & 1); } \
        CP_COMMIT(); \
        CP_WAIT1(); \
        __syncthreads(); \
        GEMM_COMPUTE_CHUNK((uint32_t)(ch & 1) * STAGE_BYTES); \
        __syncthreads(); \
    }

// ================= GEMM 1: fx = X @ Wfx + bfx -> bf16 split =================
__global__ __launch_bounds__(256) void fx_mma(const float* __restrict__ bias) {
    GEMM_PROLOG();
    const int m0 = blockIdx.y * 128;
    const int j0 = blockIdx.x * 128;
#define FX_ISSUE(ch, s) ISSUE_256(d_xs_h, d_xs_l, d_wfx_h, d_wfx_l, m0, j0, (ch) * 64, s)
    PIPELINE(4, FX_ISSUE);
#undef FX_ISSUE
#pragma unroll
    for (int mi = 0; mi < 2; mi++) {
        int row0 = m0 + wm + mi * 16 + g;
#pragma unroll
        for (int ni = 0; ni < 8; ni++) {
            int col = j0 + wn + ni * 8 + tq * 2;
            float2 bb = *(const float2*)&bias[col];
            uint32_t hh, ll;
            split2(c[mi][ni][0] + bb.x, c[mi][ni][1] + bb.y, hh, ll);
            *(uint32_t*)&d_fx_h[(size_t)row0 * 512 + col] = hh;
            *(uint32_t*)&d_fx_l[(size_t)row0 * 512 + col] = ll;
            split2(c[mi][ni][2] + bb.x, c[mi][ni][3] + bb.y, hh, ll);
            *(uint32_t*)&d_fx_h[(size_t)(row0 + 8) * 512 + col] = hh;
            *(uint32_t*)&d_fx_l[(size_t)(row0 + 8) * 512 + col] = ll;
        }
    }
}

// ================= GEMM 2: logits, fused softmax -> d_sw bf16 split =================
__global__ __launch_bounds__(256) void logit_mma(const float* __restrict__ temperature) {
    GEMM_PROLOG();
    const int m0 = blockIdx.y * 128;
    const int j0 = blockIdx.x * 128;
#define LG_ISSUE(ch, s) ISSUE_256(d_xs_h, d_xs_l, d_wls_h, d_wls_l, m0, j0, (ch) * 64, s)
    PIPELINE(4, LG_ISSUE);
#undef LG_ISSUE
    const int h = (j0 >> 6) + (w >> 2);
    float tp = temperature[h];
    tp = fminf(fmaxf(tp, 0.1f), 5.0f);
    const float invt = 1.f / tp;
    float2 blv[8];
#pragma unroll
    for (int ni = 0; ni < 8; ni++)
        blv[ni] = *(const float2*)&d_bls[j0 + wn + ni * 8 + tq * 2];
#pragma unroll
    for (int mi = 0; mi < 2; mi++)
#pragma unroll
        for (int ni = 0; ni < 8; ni++) {
            c[mi][ni][0] = (c[mi][ni][0] + blv[ni].x) * invt;
            c[mi][ni][1] = (c[mi][ni][1] + blv[ni].y) * invt;
            c[mi][ni][2] = (c[mi][ni][2] + blv[ni].x) * invt;
            c[mi][ni][3] = (c[mi][ni][3] + blv[ni].y) * invt;
        }
#pragma unroll
    for (int mi = 0; mi < 2; mi++)
#pragma unroll
        for (int half = 0; half < 2; half++) {
            const int ci = half * 2;
            float mx = -1e30f;
#pragma unroll
            for (int ni = 0; ni < 8; ni++)
                mx = fmaxf(mx, fmaxf(c[mi][ni][ci], c[mi][ni][ci + 1]));
            mx = fmaxf(mx, __shfl_xor_sync(0xffffffffu, mx, 1));
            mx = fmaxf(mx, __shfl_xor_sync(0xffffffffu, mx, 2));
            float s = 0.f;
#pragma unroll
            for (int ni = 0; ni < 8; ni++) {
                float e0 = __expf(c[mi][ni][ci] - mx);
                float e1 = __expf(c[mi][ni][ci + 1] - mx);
                c[mi][ni][ci] = e0; c[mi][ni][ci + 1] = e1;
                s += e0 + e1;
            }
            s += __shfl_xor_sync(0xffffffffu, s, 1);
            s += __shfl_xor_sync(0xffffffffu, s, 2);
            float inv = 1.f / s;
            int row = m0 + wm + mi * 16 + half * 8 + g;
            int b = row >> 15, n = row & (N_ - 1);
            size_t base = ((size_t)(b * H_ + h) * N_ + n) * 64;
#pragma unroll
            for (int ni = 0; ni < 8; ni++) {
                size_t idx = base + ni * 8 + tq * 2;
                uint32_t hh, ll;
                split2(c[mi][ni][ci] * inv, c[mi][ni][ci + 1] * inv, hh, ll);
                *(uint32_t*)&d_sw_h[idx] = hh;
                *(uint32_t*)&d_sw_l[idx] = ll;
            }
        }
}

// ================= GEMM 3: out[b] = sw[b] (N x 512) @ wot[b] (512 x 256) + bo =================
__global__ __launch_bounds__(256) void final_mma(const float* __restrict__ bo,
                                                 float* __restrict__ out) {
    GEMM_PROLOG();
    const int m0 = blockIdx.y * 128;
    const int j0 = blockIdx.x * 128;
    const int bb_ = m0 >> 15;
    const int n0 = m0 & (N_ - 1);
#define FN_ISSUE(ch, s) \
    { \
        uint32_t so = sb + (uint32_t)(s) * STAGE_BYTES; \
        const int k0 = (ch) * 64; \
        _Pragma("unroll") for (int i = 0; i < 4; i++) { \
            int e = i * 256 + t, r = e >> 3, q = e & 7; \
            uint32_t off = SWX(r, q * 16); \
            size_t aidx = ((size_t)(bb_ * H_ + (ch)) * N_ + n0 + r) * 64 + q * 8; \
            cpa16(so + off,         &d_sw_h[aidx]); \
            cpa16(so + 16384 + off, &d_sw_l[aidx]); \
            size_t bidx = ((size_t)bb_ * 256 + j0 + r) * 512 + k0 + q * 8; \
            cpa16(so + 32768 + off, &d_wot_h[bidx]); \
            cpa16(so + 49152 + off, &d_wot_l[bidx]); \
        } \
    }
    PIPELINE(8, FN_ISSUE);
#undef FN_ISSUE
#pragma unroll
    for (int mi = 0; mi < 2; mi++) {
        int row0 = m0 + wm + mi * 16 + g;
#pragma unroll
        for (int ni = 0; ni < 8; ni++) {
            int col = j0 + wn + ni * 8 + tq * 2;
            float2 bbv = *(const float2*)&bo[col];
            float2 o0 = { c[mi][ni][0] + bbv.x, c[mi][ni][1] + bbv.y };
            float2 o1 = { c[mi][ni][2] + bbv.x, c[mi][ni][3] + bbv.y };
            *(float2*)&out[(size_t)row0 * 256 + col] = o0;
            *(float2*)&out[(size_t)(row0 + 8) * 256 + col] = o1;
        }
    }
}

// ================= token aggregation via tensor cores =================
// token[g][c] = sum_n sw[n][g] * fx[n][c];  colsum[g] = sum_n sw[n][g]
// grid (16 k-splits, 32 bh); block 256 (8 warps: 2 g-groups x 4 c-groups)
// smem: 2 stages x 32KB: [sw_h 8K][sw_l 8K][fx_h 8K][fx_l 8K]
#define TOK_STAGE 32768
#define TOK_SMEM  65536
__global__ __launch_bounds__(256) void token_mma(int which_x) {
    extern __shared__ char smem[];
    const uint32_t sb = smem_u32(smem);
    float* tok = which_x ? d_tokx : d_tokc;
    float* cs  = which_x ? d_csx  : d_csc;
    const int bh = blockIdx.y;
    const int b = bh >> 3, h = bh & 7;
    const int n0 = blockIdx.x * 2048;
    const int t = threadIdx.x;
    const int w = t >> 5, lane = t & 31;
    const int wg = (w & 1) * 32;        // g offset
    const int wc = (w >> 1) * 16;       // c offset
    const int lg = lane >> 3, l8 = lane & 7;

    // trans-ldmatrix addresses: A from sw[n][g] tile, B from fx[n][c] tile
    const int rowA = (lg >> 1) * 8 + l8;
    uint32_t offA[2];
#pragma unroll
    for (int mi = 0; mi < 2; mi++) {
        int goff = wg + mi * 16 + (lg & 1) * 8;
        offA[mi] = rowA * 128 + ((goff * 2) ^ ((rowA & 7) << 4));
    }
    const int rowB = (lg & 1) * 8 + l8;
    const int coff = wc + (lg >> 1) * 8;
    const uint32_t offB = rowB * 128 + ((coff * 2) ^ ((rowB & 7) << 4));

    // colsum ownership: g = t&63, row-range = (t>>6)*16
    const int gcs = t & 63, rq = (t >> 6) * 16;
    float csacc = 0.f;

    float c[2][2][4];
#pragma unroll
    for (int mi = 0; mi < 2; mi++)
#pragma unroll
        for (int ni = 0; ni < 2; ni++)
#pragma unroll
            for (int q = 0; q < 4; q++) c[mi][ni][q] = 0.f;

#define TOK_ISSUE(ch, s) \
    { \
        uint32_t so = sb + (uint32_t)(s) * TOK_STAGE; \
        const int nn = n0 + (ch) * 64; \
        _Pragma("unroll") for (int i = 0; i < 2; i++) { \
            int e = i * 256 + t, r = e >> 3, q = e & 7; \
            uint32_t off = SWX(r, q * 16); \
            size_t sidx = ((size_t)bh * N_ + nn + r) * 64 + q * 8; \
            cpa16(so + off,         &d_sw_h[sidx]); \
            cpa16(so + 8192 + off,  &d_sw_l[sidx]); \
            size_t fidx = ((size_t)(b * N_ + nn + r)) * 512 + h * 64 + q * 8; \
            cpa16(so + 16384 + off, &d_fx_h[fidx]); \
            cpa16(so + 24576 + off, &d_fx_l[fidx]); \
        } \
    }

    TOK_ISSUE(0, 0);
    CP_COMMIT();
    for (int ch = 0; ch < 32; ch++) {
        if (ch + 1 < 32) { TOK_ISSUE(ch + 1, (ch + 1) & 1); }
        CP_COMMIT();
        CP_WAIT1();
        __syncthreads();
        const uint32_t so = (uint32_t)(ch & 1) * TOK_STAGE;
#pragma unroll
        for (int ks = 0; ks < 4; ks++) {
            const uint32_t kso = so + ks * 2048;
            uint32_t ah[2][4], al[2][4], rbh[4], rbl[4];
#pragma unroll
            for (int mi = 0; mi < 2; mi++) {
                ldsm4t(ah[mi], sb + kso + offA[mi]);
                ldsm4t(al[mi], sb + 8192 + kso + offA[mi]);
            }
            ldsm4t(rbh, sb + 16384 + kso + offB);
            ldsm4t(rbl, sb + 24576 + kso + offB);
            uint32_t bfh[2][2] = {{rbh[0], rbh[1]}, {rbh[2], rbh[3]}};
            uint32_t bfl[2][2] = {{rbl[0], rbl[1]}, {rbl[2], rbl[3]}};
#pragma unroll
            for (int mi = 0; mi < 2; mi++)
#pragma unroll
                for (int ni = 0; ni < 2; ni++) {
                    mma16816(c[mi][ni], ah[mi], bfh[ni]);
                    mma16816(c[mi][ni], ah[mi], bfl[ni]);
                    mma16816(c[mi][ni], al[mi], bfh[ni]);
                }
        }
        // colsum: rows rq..rq+15 of this tile, column gcs
#pragma unroll
        for (int r = 0; r < 16; r++) {
            int rr = rq + r;
            uint32_t off = so + rr * 128 + (((uint32_t)(gcs * 2)) ^ (((uint32_t)(rr & 7)) << 4));
            float vh = __bfloat162float(*(const __nv_bfloat16*)(smem + off));
            float vl = __bfloat162float(*(const __nv_bfloat16*)(smem + 8192 + off));
            csacc += vh + vl;
        }
        __syncthreads();
    }
#undef TOK_ISSUE
    // epilogue: atomic accumulate
    const int grow = lane >> 2, cpair = (lane & 3) * 2;
#pragma unroll
    for (int mi = 0; mi < 2; mi++) {
        int gg = wg + mi * 16 + grow;
#pragma unroll
        for (int ni = 0; ni < 2; ni++) {
            int col = wc + ni * 8 + cpair;
            atomicAdd(&tok[bh * 4096 + gg * 64 + col],       c[mi][ni][0]);
            atomicAdd(&tok[bh * 4096 + gg * 64 + col + 1],   c[mi][ni][1]);
            atomicAdd(&tok[bh * 4096 + (gg + 8) * 64 + col],     c[mi][ni][2]);
            atomicAdd(&tok[bh * 4096 + (gg + 8) * 64 + col + 1], c[mi][ni][3]);
        }
    }
    atomicAdd(&cs[bh * 64 + gcs], csacc);
}

// ================= prep kernels =================
__global__ void presplit_x(const float* __restrict__ X) {
    size_t i = (size_t)blockIdx.x * 256 + threadIdx.x;   // indexes float4 groups
    float4 v = ((const float4*)X)[i];
    uint2 hh, ll;
    split2(v.x, v.y, hh.x, ll.x);
    split2(v.z, v.w, hh.y, ll.y);
    ((uint2*)d_xs_h)[i] = hh;
    ((uint2*)d_xs_l)[i] = ll;
}

__global__ void zero_kernel() {
    int i = blockIdx.x * blockDim.x + threadIdx.x;
    if (i < BH_ * M_ * CH_) { d_tokx[i] = 0.f; d_tokc[i] = 0.f; }
    if (i < BH_ * M_)       { d_csx[i]  = 0.f; d_csc[i]  = 0.f; }
}

__global__ void prep_wfx(const float* __restrict__ W) {   // W [256][512] -> W^T split
    int j = blockIdx.x, cc = threadIdx.x;
    float wv = W[cc * 512 + j];
    __nv_bfloat16 h = __float2bfloat16(wv);
    d_wfx_h[j * 256 + cc] = h;
    d_wfx_l[j * 256 + cc] = __float2bfloat16(wv - __bfloat162float(h));
}

// Wls^T[j=h*64+m][c] = sum_e Wx[c][h*64+e] * Wslice[e][m]; also bls[j]
__global__ void prep_wls(const float* __restrict__ Wx, const float* __restrict__ Wslice,
                         const float* __restrict__ bx, const float* __restrict__ bslice) {
    extern __shared__ float sm[];
    float* ws = sm;            // [64]
    float* wx = sm + 64;       // [256][68]
    int j = blockIdx.x, h = j >> 6, m = j & 63, t = threadIdx.x;
    if (t < 64) ws[t] = Wslice[t * 64 + m];
    for (int i = t; i < 256 * 16; i += 256) {
        int r = i >> 4, q = i & 15;
        *(float4*)&wx[r * 68 + q * 4] = *(const float4*)&Wx[r * 512 + h * 64 + q * 4];
    }
    __syncthreads();
    float acc = 0.f;
#pragma unroll 8
    for (int e = 0; e < 64; e++) acc += wx[t * 68 + e] * ws[e];
    __nv_bfloat16 hh = __float2bfloat16(acc);
    d_wls_h[j * 256 + t] = hh;
    d_wls_l[j * 256 + t] = __float2bfloat16(acc - __bfloat162float(hh));
    if (t == 0) {
        float bb = bslice[m];
        for (int e = 0; e < 64; e++) bb += bx[h * 64 + e] * ws[e];
        d_bls[j] = bb;
    }
}

__global__ void prep_wot() {   // d_wot[b][512][256] -> [b][256][512] split
    int bc = blockIdx.x;
    int b = bc >> 8, cc = bc & 255, t = threadIdx.x;   // 512 threads
    float wv = d_wot[((size_t)b * 512 + t) * 256 + cc];
    __nv_bfloat16 h = __float2bfloat16(wv);
    d_wot_h[(size_t)bc * 512 + t] = h;
    d_wot_l[(size_t)bc * 512 + t] = __float2bfloat16(wv - __bfloat162float(h));
}

// ================= tiny attention + Wo refactor =================
__global__ void attn_kernel(const float* __restrict__ Wq,
                            const float* __restrict__ Wk,
                            const float* __restrict__ Wv) {
    extern __shared__ float sm[];
    float* A  = sm;
    float* Ks = sm + 64 * 65;
    float* Vs = Ks + 64 * 64;
    const int bh = blockIdx.x;
    const int g = threadIdx.x;

    for (int idx = g; idx < 4096; idx += 64) {
        int r = idx >> 6, cc = idx & 63;
        A[r * 65 + cc] = d_tokc[bh * 4096 + idx] / (d_csc[bh * 64 + r] + 1e-5f);
    }
    __syncthreads();
    {
        float ka[64], va[64];
#pragma unroll
        for (int cc = 0; cc < 64; cc++) { ka[cc] = 0.f; va[cc] = 0.f; }
        for (int e = 0; e < 64; e++) {
            float te = A[g * 65 + e];
#pragma unroll
            for (int cc = 0; cc < 64; cc++) {
                ka[cc] += te * Wk[e * 64 + cc];
                va[cc] += te * Wv[e * 64 + cc];
            }
        }
#pragma unroll
        for (int cc = 0; cc < 64; cc++) { Ks[g * 64 + cc] = ka[cc]; Vs[g * 64 + cc] = va[cc]; }
    }
    __syncthreads();
    for (int idx = g; idx < 4096; idx += 64) {
        int r = idx >> 6, cc = idx & 63;
        A[r * 65 + cc] = d_tokx[bh * 4096 + idx] / (d_csx[bh * 64 + r] + 1e-5f);
    }
    __syncthreads();

    float q[64];
#pragma unroll
    for (int cc = 0; cc < 64; cc++) q[cc] = 0.f;
    for (int e = 0; e < 64; e++) {
        float te = A[g * 65 + e];
#pragma unroll
        for (int cc = 0; cc < 64; cc++) q[cc] += te * Wq[e * 64 + cc];
    }
    __syncthreads();
    float* srow = &A[g * 65];
    float mx = -1e30f;
    for (int m = 0; m < 64; m++) {
        float a2 = 0.f;
#pragma unroll
        for (int cc = 0; cc < 64; cc++) a2 += q[cc] * Ks[m * 64 + cc];
        a2 *= 0.125f;
        srow[m] = a2;
        mx = fmaxf(mx, a2);
    }
    float sum = 0.f;
    for (int m = 0; m < 64; m++) { float e = __expf(srow[m] - mx); srow[m] = e; sum += e; }
    float inv = 1.f / sum;
    float o[64];
#pragma unroll
    for (int cc = 0; cc < 64; cc++) o[cc] = 0.f;
    for (int m = 0; m < 64; m++) {
        float p = srow[m] * inv;
#pragma unroll
        for (int cc = 0; cc < 64; cc++) o[cc] += p * Vs[m * 64 + cc];
    }
    float invx = 1.f / (d_csx[bh * 64 + g] + 1e-5f);
#pragma unroll
    for (int cc = 0; cc < 64; cc++) d_outsc[bh * 4096 + g * 64 + cc] = o[cc] * invx;
}

__global__ __launch_bounds__(256) void wot_kernel(const float* __restrict__ Wo) {
    const int bhg = blockIdx.x;
    const int hg = bhg & (H_ * M_ - 1);
    const int h = hg >> 6;
    __shared__ float orow[64];
    const int t = threadIdx.x;
    if (t < 64) orow[t] = d_outsc[bhg * 64 + t];
    __syncthreads();
    float acc = 0.f;
#pragma unroll 8
    for (int cc = 0; cc < 64; cc++) acc += orow[cc] * Wo[(h * 64 + cc) * 256 + t];
    d_wot[(size_t)bhg * 256 + t] = acc;
}

// ================= launcher =================
extern "C" void kernel_launch(void* const* d_in, const int* in_sizes, int n_in,
                              void* d_out, int out_size) {
    const float* x      = (const float*)d_in[0];
    const float* xc     = (const float*)d_in[1];
    const float* Wfx    = (const float*)d_in[2];
    const float* bfx    = (const float*)d_in[3];
    const float* Wx     = (const float*)d_in[4];
    const float* bx     = (const float*)d_in[5];
    const float* Wslice = (const float*)d_in[6];
    const float* bslice = (const float*)d_in[7];
    const float* temp   = (const float*)d_in[8];
    const float* Wq     = (const float*)d_in[9];
    const float* Wk     = (const float*)d_in[10];
    const float* Wv     = (const float*)d_in[11];
    const float* Wo     = (const float*)d_in[12];
    const float* bo     = (const float*)d_in[13];
    float* out = (float*)d_out;

    const int attn_smem = (64 * 65 + 2 * 64 * 64) * (int)sizeof(float);
    const int wls_smem  = (64 + 256 * 68) * (int)sizeof(float);
    cudaFuncSetAttribute(attn_kernel, cudaFuncAttributeMaxDynamicSharedMemorySize, attn_smem);
    cudaFuncSetAttribute(prep_wls,    cudaFuncAttributeMaxDynamicSharedMemorySize, wls_smem);
    cudaFuncSetAttribute(fx_mma,      cudaFuncAttributeMaxDynamicSharedMemorySize, GEMM_SMEM);
    cudaFuncSetAttribute(logit_mma,   cudaFuncAttributeMaxDynamicSharedMemorySize, GEMM_SMEM);
    cudaFuncSetAttribute(final_mma,   cudaFuncAttributeMaxDynamicSharedMemorySize, GEMM_SMEM);
    cudaFuncSetAttribute(token_mma,   cudaFuncAttributeMaxDynamicSharedMemorySize, TOK_SMEM);

    zero_kernel<<<512, 256>>>();
    prep_wfx<<<512, 256>>>(Wfx);
    prep_wls<<<512, 256, wls_smem>>>(Wx, Wslice, bx, bslice);

    dim3 ggrid(4, ROWS_ / 128);
    dim3 tokgrid(16, BH_);
    const int ps_blocks = (int)((size_t)ROWS_ * 256 / 4 / 256);

    // ---- cross pass ----
    presplit_x<<<ps_blocks, 256>>>(xc);
    fx_mma<<<ggrid, 256, GEMM_SMEM>>>(bfx);
    logit_mma<<<ggrid, 256, GEMM_SMEM>>>(temp);
    token_mma<<<tokgrid, 256, TOK_SMEM>>>(0);

    // ---- x pass ----
    presplit_x<<<ps_blocks, 256>>>(x);
    fx_mma<<<ggrid, 256, GEMM_SMEM>>>(bfx);
    logit_mma<<<ggrid, 256, GEMM_SMEM>>>(temp);
    token_mma<<<tokgrid, 256, TOK_SMEM>>>(1);

    // ---- tiny attention + epilogue ----
    attn_kernel<<<BH_, 64, attn_smem>>>(Wq, Wk, Wv);
    wot_kernel<<<B_ * H_ * M_, 256>>>(Wo);
    prep_wot<<<B_ * C_, 512>>>();
    final_mma<<<dim3(2, ROWS_ / 128), 256, GEMM_SMEM>>>(bo, out);
}

// round 6
// speedup vs baseline: 3.2212x; 1.0881x over previous
#include <cuda_runtime.h>
#include <cuda_bf16.h>
#include <cstdint>

#define B_ 4
#define N_ 32768
#define C_ 256
#define H_ 8
#define CH_ 64
#define M_ 64
#define INNER_ 512
#define ROWS_ (B_*N_)          // 131072
#define BH_ (B_*N_/N_*H_)      // 32

// ================= static scratch =================
__device__ __nv_bfloat16 d_fx_h[(size_t)ROWS_ * 512]; // fx split (token_mma)
__device__ __nv_bfloat16 d_fx_l[(size_t)ROWS_ * 512];
__device__ __nv_bfloat16 d_sw_h[(size_t)BH_ * N_ * M_];// sw split (token_mma + final_mma)
__device__ __nv_bfloat16 d_sw_l[(size_t)BH_ * N_ * M_];
__device__ __nv_bfloat16 d_xs_h[(size_t)ROWS_ * 256];  // current input split
__device__ __nv_bfloat16 d_xs_l[(size_t)ROWS_ * 256];
__device__ float d_tokx[BH_ * M_ * CH_];
__device__ float d_tokc[BH_ * M_ * CH_];
__device__ float d_csx[BH_ * M_];
__device__ float d_csc[BH_ * M_];
__device__ float d_outsc[BH_ * M_ * CH_];
__device__ float d_wot[B_ * INNER_ * C_];
__device__ float d_bls[INNER_];
__device__ __nv_bfloat16 d_wfx_h[INNER_ * C_];         // Wfx^T split  [512][256]
__device__ __nv_bfloat16 d_wfx_l[INNER_ * C_];
__device__ __nv_bfloat16 d_wls_h[INNER_ * C_];         // (Wx@Wslice)^T split [512][256]
__device__ __nv_bfloat16 d_wls_l[INNER_ * C_];
__device__ __nv_bfloat16 d_wot_h[B_ * C_ * INNER_];    // wot^T split [b][256][512]
__device__ __nv_bfloat16 d_wot_l[B_ * C_ * INNER_];

// ================= helpers =================
__device__ __forceinline__ uint32_t smem_u32(const void* p) {
    uint32_t a;
    asm("{ .reg .u64 t; cvta.to.shared.u64 t, %1; cvt.u32.u64 %0, t; }" : "=r"(a) : "l"(p));
    return a;
}
__device__ __forceinline__ void ldsm4(uint32_t* r, uint32_t addr) {
    asm volatile("ldmatrix.sync.aligned.m8n8.x4.shared.b16 {%0,%1,%2,%3}, [%4];"
                 : "=r"(r[0]), "=r"(r[1]), "=r"(r[2]), "=r"(r[3]) : "r"(addr));
}
__device__ __forceinline__ void ldsm4t(uint32_t* r, uint32_t addr) {
    asm volatile("ldmatrix.sync.aligned.m8n8.x4.trans.shared.b16 {%0,%1,%2,%3}, [%4];"
                 : "=r"(r[0]), "=r"(r[1]), "=r"(r[2]), "=r"(r[3]) : "r"(addr));
}
__device__ __forceinline__ void mma16816(float* c, const uint32_t* a, const uint32_t* b) {
    asm volatile("mma.sync.aligned.m16n8k16.row.col.f32.bf16.bf16.f32 "
                 "{%0,%1,%2,%3}, {%4,%5,%6,%7}, {%8,%9}, {%0,%1,%2,%3};"
                 : "+f"(c[0]), "+f"(c[1]), "+f"(c[2]), "+f"(c[3])
                 : "r"(a[0]), "r"(a[1]), "r"(a[2]), "r"(a[3]), "r"(b[0]), "r"(b[1]));
}
__device__ __forceinline__ void split2(float x, float y, uint32_t& hi, uint32_t& lo) {
    __nv_bfloat16 hx = __float2bfloat16(x), hy = __float2bfloat16(y);
    float rx = x - __bfloat162float(hx), ry = y - __bfloat162float(hy);
    __nv_bfloat16 lx = __float2bfloat16(rx), ly = __float2bfloat16(ry);
    hi = (uint32_t)__bfloat16_as_ushort(hx) | ((uint32_t)__bfloat16_as_ushort(hy) << 16);
    lo = (uint32_t)__bfloat16_as_ushort(lx) | ((uint32_t)__bfloat16_as_ushort(ly) << 16);
}
__device__ __forceinline__ void cpa16(uint32_t dst, const void* src) {
    asm volatile("cp.async.cg.shared.global [%0], [%1], 16;" :: "r"(dst), "l"(src));
}
#define CP_COMMIT() asm volatile("cp.async.commit_group;" ::: "memory")
#define CP_WAIT1()  asm volatile("cp.async.wait_group 1;" ::: "memory")
#define CP_WAIT2()  asm volatile("cp.async.wait_group 2;" ::: "memory")

// GEMM smem: 3 stages x 32KB: [A_hi 8K][A_lo 8K][B_hi 8K][B_lo 8K], 64B rows
#define STAGE_BYTES 32768
#define GEMM_SMEM   98304
// 64-byte-row swizzle: XOR byte bits[5:4] with row bits[2:1]  (ldmatrix conflict-free)
#define SWX64(r, byte) ((uint32_t)((r) * 64 + ((byte) ^ ((((r) >> 1) & 3) << 4))))
// 128-byte-row swizzle (token kernel)
#define SWX(r, byte) ((uint32_t)((r) * 128 + ((byte) ^ (((r) & 7) << 4))))

// ===================================================================
// warp layout: 8 warps; warp_m = w&3 (32 rows each), warp_n = w>>2 (64 cols each)
// ===================================================================
#define GEMM_PROLOG() \
    extern __shared__ char smem[]; \
    const uint32_t sb = smem_u32(smem); \
    const int t = threadIdx.x; \
    const int w = t >> 5, lane = t & 31; \
    const int wm = (w & 3) * 32, wn = (w >> 2) * 64; \
    const int g = lane >> 2, tq = lane & 3; \
    const int ar_ = lane & 15, akh_ = lane >> 4; \
    const int qd_ = lane >> 3, bl8_ = lane & 7; \
    uint32_t abase[2], axr[2], bbase[4], bxr[4]; \
    _Pragma("unroll") for (int mi = 0; mi < 2; mi++) { \
        int row = wm + mi * 16 + ar_; \
        abase[mi] = row * 64; axr[mi] = ((row >> 1) & 3) << 4; \
    } \
    _Pragma("unroll") for (int nb = 0; nb < 4; nb++) { \
        int row = wn + nb * 16 + (qd_ >> 1) * 8 + bl8_; \
        bbase[nb] = row * 64; bxr[nb] = ((row >> 1) & 3) << 4; \
    } \
    const uint32_t bk16_ = (qd_ & 1) * 16; \
    const uint32_t ak16_ = akh_ * 16; \
    float c[2][8][4]; \
    _Pragma("unroll") for (int mi = 0; mi < 2; mi++) \
    _Pragma("unroll") for (int ni = 0; ni < 8; ni++) \
    _Pragma("unroll") for (int q = 0; q < 4; q++) c[mi][ni][q] = 0.f;

#define GEMM_COMPUTE_CHUNK32(soff) \
    _Pragma("unroll") for (int ks = 0; ks < 2; ks++) { \
        uint32_t ah[2][4], al[2][4], bh[8][2], bl[8][2]; \
        const uint32_t ka = ks * 32 + ak16_; \
        const uint32_t kb = ks * 32 + bk16_; \
        _Pragma("unroll") for (int mi = 0; mi < 2; mi++) { \
            uint32_t off = (soff) + abase[mi] + (ka ^ axr[mi]); \
            ldsm4(ah[mi], sb + off); \
            ldsm4(al[mi], sb + 8192 + off); \
        } \
        _Pragma("unroll") for (int nb = 0; nb < 4; nb++) { \
            uint32_t off = (soff) + bbase[nb] + (kb ^ bxr[nb]); \
            uint32_t rh[4], rl[4]; \
            ldsm4(rh, sb + 16384 + off); \
            ldsm4(rl, sb + 24576 + off); \
            bh[nb*2][0] = rh[0]; bh[nb*2][1] = rh[1]; \
            bh[nb*2+1][0] = rh[2]; bh[nb*2+1][1] = rh[3]; \
            bl[nb*2][0] = rl[0]; bl[nb*2][1] = rl[1]; \
            bl[nb*2+1][0] = rl[2]; bl[nb*2+1][1] = rl[3]; \
        } \
        _Pragma("unroll") for (int mi = 0; mi < 2; mi++) \
        _Pragma("unroll") for (int ni = 0; ni < 8; ni++) { \
            mma16816(c[mi][ni], ah[mi], bh[ni]); \
            mma16816(c[mi][ni], ah[mi], bl[ni]); \
            mma16816(c[mi][ni], al[mi], bh[ni]); \
        } \
    }

// issue one 32-wide k-chunk: A (Ahp,Alp) stride 256, B (Bhp,Blp) stride 256
#define ISSUE_K32(Ahp, Alp, Bhp, Blp, m0, j0, k0, s) \
    { \
        uint32_t so = sb + (uint32_t)(s) * STAGE_BYTES; \
        _Pragma("unroll") for (int i = 0; i < 2; i++) { \
            int e = i * 256 + t, r = e >> 2, q = e & 3; \
            uint32_t off = SWX64(r, q * 16); \
            cpa16(so + off,         &(Ahp)[(size_t)((m0) + r) * 256 + (k0) + q * 8]); \
            cpa16(so + 8192 + off,  &(Alp)[(size_t)((m0) + r) * 256 + (k0) + q * 8]); \
            cpa16(so + 16384 + off, &(Bhp)[(size_t)((j0) + r) * 256 + (k0) + q * 8]); \
            cpa16(so + 24576 + off, &(Blp)[(size_t)((j0) + r) * 256 + (k0) + q * 8]); \
        } \
    }

#define PIPELINE3(NC, ISSUE_CH) \
    ISSUE_CH(0, 0); \
    CP_COMMIT(); \
    ISSUE_CH(1, 1); \
    CP_COMMIT(); \
    for (int ch = 0; ch < (NC); ch++) { \
        if (ch + 2 < (NC)) { ISSUE_CH(ch + 2, (ch + 2) % 3); } \
        CP_COMMIT(); \
        CP_WAIT2(); \
        __syncthreads(); \
        GEMM_COMPUTE_CHUNK32((uint32_t)(ch % 3) * STAGE_BYTES); \
        __syncthreads(); \
    }

// ================= GEMM 1: fx = X @ Wfx + bfx -> bf16 split =================
__global__ __launch_bounds__(256, 2) void fx_mma(const float* __restrict__ bias) {
    GEMM_PROLOG();
    const int m0 = blockIdx.y * 128;
    const int j0 = blockIdx.x * 128;
#define FX_ISSUE(ch, s) ISSUE_K32(d_xs_h, d_xs_l, d_wfx_h, d_wfx_l, m0, j0, (ch) * 32, s)
    PIPELINE3(8, FX_ISSUE);
#undef FX_ISSUE
#pragma unroll
    for (int mi = 0; mi < 2; mi++) {
        int row0 = m0 + wm + mi * 16 + g;
#pragma unroll
        for (int ni = 0; ni < 8; ni++) {
            int col = j0 + wn + ni * 8 + tq * 2;
            float2 bb = *(const float2*)&bias[col];
            uint32_t hh, ll;
            split2(c[mi][ni][0] + bb.x, c[mi][ni][1] + bb.y, hh, ll);
            *(uint32_t*)&d_fx_h[(size_t)row0 * 512 + col] = hh;
            *(uint32_t*)&d_fx_l[(size_t)row0 * 512 + col] = ll;
            split2(c[mi][ni][2] + bb.x, c[mi][ni][3] + bb.y, hh, ll);
            *(uint32_t*)&d_fx_h[(size_t)(row0 + 8) * 512 + col] = hh;
            *(uint32_t*)&d_fx_l[(size_t)(row0 + 8) * 512 + col] = ll;
        }
    }
}

// ================= GEMM 2: logits, fused softmax -> d_sw bf16 split =================
__global__ __launch_bounds__(256, 2) void logit_mma(const float* __restrict__ temperature) {
    GEMM_PROLOG();
    const int m0 = blockIdx.y * 128;
    const int j0 = blockIdx.x * 128;
#define LG_ISSUE(ch, s) ISSUE_K32(d_xs_h, d_xs_l, d_wls_h, d_wls_l, m0, j0, (ch) * 32, s)
    PIPELINE3(8, LG_ISSUE);
#undef LG_ISSUE
    const int h = (j0 >> 6) + (w >> 2);
    float tp = temperature[h];
    tp = fminf(fmaxf(tp, 0.1f), 5.0f);
    const float invt = 1.f / tp;
    float2 blv[8];
#pragma unroll
    for (int ni = 0; ni < 8; ni++)
        blv[ni] = *(const float2*)&d_bls[j0 + wn + ni * 8 + tq * 2];
#pragma unroll
    for (int mi = 0; mi < 2; mi++)
#pragma unroll
        for (int ni = 0; ni < 8; ni++) {
            c[mi][ni][0] = (c[mi][ni][0] + blv[ni].x) * invt;
            c[mi][ni][1] = (c[mi][ni][1] + blv[ni].y) * invt;
            c[mi][ni][2] = (c[mi][ni][2] + blv[ni].x) * invt;
            c[mi][ni][3] = (c[mi][ni][3] + blv[ni].y) * invt;
        }
#pragma unroll
    for (int mi = 0; mi < 2; mi++)
#pragma unroll
        for (int half = 0; half < 2; half++) {
            const int ci = half * 2;
            float mx = -1e30f;
#pragma unroll
            for (int ni = 0; ni < 8; ni++)
                mx = fmaxf(mx, fmaxf(c[mi][ni][ci], c[mi][ni][ci + 1]));
            mx = fmaxf(mx, __shfl_xor_sync(0xffffffffu, mx, 1));
            mx = fmaxf(mx, __shfl_xor_sync(0xffffffffu, mx, 2));
            float s = 0.f;
#pragma unroll
            for (int ni = 0; ni < 8; ni++) {
                float e0 = __expf(c[mi][ni][ci] - mx);
                float e1 = __expf(c[mi][ni][ci + 1] - mx);
                c[mi][ni][ci] = e0; c[mi][ni][ci + 1] = e1;
                s += e0 + e1;
            }
            s += __shfl_xor_sync(0xffffffffu, s, 1);
            s += __shfl_xor_sync(0xffffffffu, s, 2);
            float inv = 1.f / s;
            int row = m0 + wm + mi * 16 + half * 8 + g;
            int b = row >> 15, n = row & (N_ - 1);
            size_t base = ((size_t)(b * H_ + h) * N_ + n) * 64;
#pragma unroll
            for (int ni = 0; ni < 8; ni++) {
                size_t idx = base + ni * 8 + tq * 2;
                uint32_t hh, ll;
                split2(c[mi][ni][ci] * inv, c[mi][ni][ci + 1] * inv, hh, ll);
                *(uint32_t*)&d_sw_h[idx] = hh;
                *(uint32_t*)&d_sw_l[idx] = ll;
            }
        }
}

// ================= GEMM 3: out[b] = sw[b] (N x 512) @ wot[b] (512 x 256) + bo =================
__global__ __launch_bounds__(256, 2) void final_mma(const float* __restrict__ bo,
                                                    float* __restrict__ out) {
    GEMM_PROLOG();
    const int m0 = blockIdx.y * 128;
    const int j0 = blockIdx.x * 128;
    const int bb_ = m0 >> 15;
    const int n0 = m0 & (N_ - 1);
#define FN_ISSUE(ch, s) \
    { \
        uint32_t so = sb + (uint32_t)(s) * STAGE_BYTES; \
        const int hh_ = (ch) >> 1, g0_ = ((ch) & 1) * 32; \
        const int k0 = (ch) * 32; \
        _Pragma("unroll") for (int i = 0; i < 2; i++) { \
            int e = i * 256 + t, r = e >> 2, q = e & 3; \
            uint32_t off = SWX64(r, q * 16); \
            size_t aidx = ((size_t)(bb_ * H_ + hh_) * N_ + n0 + r) * 64 + g0_ + q * 8; \
            cpa16(so + off,         &d_sw_h[aidx]); \
            cpa16(so + 8192 + off,  &d_sw_l[aidx]); \
            size_t bidx = ((size_t)bb_ * 256 + j0 + r) * 512 + k0 + q * 8; \
            cpa16(so + 16384 + off, &d_wot_h[bidx]); \
            cpa16(so + 24576 + off, &d_wot_l[bidx]); \
        } \
    }
    PIPELINE3(16, FN_ISSUE);
#undef FN_ISSUE
#pragma unroll
    for (int mi = 0; mi < 2; mi++) {
        int row0 = m0 + wm + mi * 16 + g;
#pragma unroll
        for (int ni = 0; ni < 8; ni++) {
            int col = j0 + wn + ni * 8 + tq * 2;
            float2 bbv = *(const float2*)&bo[col];
            float2 o0 = { c[mi][ni][0] + bbv.x, c[mi][ni][1] + bbv.y };
            float2 o1 = { c[mi][ni][2] + bbv.x, c[mi][ni][3] + bbv.y };
            *(float2*)&out[(size_t)row0 * 256 + col] = o0;
            *(float2*)&out[(size_t)(row0 + 8) * 256 + col] = o1;
        }
    }
}

// ================= token aggregation via tensor cores =================
#define TOK_STAGE 32768
#define TOK_SMEM  65536
__global__ __launch_bounds__(256) void token_mma(int which_x) {
    extern __shared__ char smem[];
    const uint32_t sb = smem_u32(smem);
    float* tok = which_x ? d_tokx : d_tokc;
    float* cs  = which_x ? d_csx  : d_csc;
    const int bh = blockIdx.y;
    const int b = bh >> 3, h = bh & 7;
    const int n0 = blockIdx.x * 2048;
    const int t = threadIdx.x;
    const int w = t >> 5, lane = t & 31;
    const int wg = (w & 1) * 32;        // g offset
    const int wc = (w >> 1) * 16;       // c offset
    const int lg = lane >> 3, l8 = lane & 7;

    const int rowA = (lg >> 1) * 8 + l8;
    uint32_t offA[2];
#pragma unroll
    for (int mi = 0; mi < 2; mi++) {
        int goff = wg + mi * 16 + (lg & 1) * 8;
        offA[mi] = rowA * 128 + ((goff * 2) ^ ((rowA & 7) << 4));
    }
    const int rowB = (lg & 1) * 8 + l8;
    const int coff = wc + (lg >> 1) * 8;
    const uint32_t offB = rowB * 128 + ((coff * 2) ^ ((rowB & 7) << 4));

    const int gcs = t & 63, rq = (t >> 6) * 16;
    float csacc = 0.f;

    float c[2][2][4];
#pragma unroll
    for (int mi = 0; mi < 2; mi++)
#pragma unroll
        for (int ni = 0; ni < 2; ni++)
#pragma unroll
            for (int q = 0; q < 4; q++) c[mi][ni][q] = 0.f;

#define TOK_ISSUE(ch, s) \
    { \
        uint32_t so = sb + (uint32_t)(s) * TOK_STAGE; \
        const int nn = n0 + (ch) * 64; \
        _Pragma("unroll") for (int i = 0; i < 2; i++) { \
            int e = i * 256 + t, r = e >> 3, q = e & 7; \
            uint32_t off = SWX(r, q * 16); \
            size_t sidx = ((size_t)bh * N_ + nn + r) * 64 + q * 8; \
            cpa16(so + off,         &d_sw_h[sidx]); \
            cpa16(so + 8192 + off,  &d_sw_l[sidx]); \
            size_t fidx = ((size_t)(b * N_ + nn + r)) * 512 + h * 64 + q * 8; \
            cpa16(so + 16384 + off, &d_fx_h[fidx]); \
            cpa16(so + 24576 + off, &d_fx_l[fidx]); \
        } \
    }

    TOK_ISSUE(0, 0);
    CP_COMMIT();
    for (int ch = 0; ch < 32; ch++) {
        if (ch + 1 < 32) { TOK_ISSUE(ch + 1, (ch + 1) & 1); }
        CP_COMMIT();
        CP_WAIT1();
        __syncthreads();
        const uint32_t so = (uint32_t)(ch & 1) * TOK_STAGE;
#pragma unroll
        for (int ks = 0; ks < 4; ks++) {
            const uint32_t kso = so + ks * 2048;
            uint32_t ah[2][4], al[2][4], rbh[4], rbl[4];
#pragma unroll
            for (int mi = 0; mi < 2; mi++) {
                ldsm4t(ah[mi], sb + kso + offA[mi]);
                ldsm4t(al[mi], sb + 8192 + kso + offA[mi]);
            }
            ldsm4t(rbh, sb + 16384 + kso + offB);
            ldsm4t(rbl, sb + 24576 + kso + offB);
            uint32_t bfh[2][2] = {{rbh[0], rbh[1]}, {rbh[2], rbh[3]}};
            uint32_t bfl[2][2] = {{rbl[0], rbl[1]}, {rbl[2], rbl[3]}};
#pragma unroll
            for (int mi = 0; mi < 2; mi++)
#pragma unroll
                for (int ni = 0; ni < 2; ni++) {
                    mma16816(c[mi][ni], ah[mi], bfh[ni]);
                    mma16816(c[mi][ni], ah[mi], bfl[ni]);
                    mma16816(c[mi][ni], al[mi], bfh[ni]);
                }
        }
#pragma unroll
        for (int r = 0; r < 16; r++) {
            int rr = rq + r;
            uint32_t off = so + rr * 128 + (((uint32_t)(gcs * 2)) ^ (((uint32_t)(rr & 7)) << 4));
            float vh = __bfloat162float(*(const __nv_bfloat16*)(smem + off));
            float vl = __bfloat162float(*(const __nv_bfloat16*)(smem + 8192 + off));
            csacc += vh + vl;
        }
        __syncthreads();
    }
#undef TOK_ISSUE
    const int grow = lane >> 2, cpair = (lane & 3) * 2;
#pragma unroll
    for (int mi = 0; mi < 2; mi++) {
        int gg = wg + mi * 16 + grow;
#pragma unroll
        for (int ni = 0; ni < 2; ni++) {
            int col = wc + ni * 8 + cpair;
            atomicAdd(&tok[bh * 4096 + gg * 64 + col],       c[mi][ni][0]);
            atomicAdd(&tok[bh * 4096 + gg * 64 + col + 1],   c[mi][ni][1]);
            atomicAdd(&tok[bh * 4096 + (gg + 8) * 64 + col],     c[mi][ni][2]);
            atomicAdd(&tok[bh * 4096 + (gg + 8) * 64 + col + 1], c[mi][ni][3]);
        }
    }
    atomicAdd(&cs[bh * 64 + gcs], csacc);
}

// ================= prep kernels =================
__global__ void presplit_x(const float* __restrict__ X) {
    size_t i = (size_t)blockIdx.x * 256 + threadIdx.x;
    float4 v = ((const float4*)X)[i];
    uint2 hh, ll;
    split2(v.x, v.y, hh.x, ll.x);
    split2(v.z, v.w, hh.y, ll.y);
    ((uint2*)d_xs_h)[i] = hh;
    ((uint2*)d_xs_l)[i] = ll;
}

__global__ void zero_kernel() {
    int i = blockIdx.x * blockDim.x + threadIdx.x;
    if (i < BH_ * M_ * CH_) { d_tokx[i] = 0.f; d_tokc[i] = 0.f; }
    if (i < BH_ * M_)       { d_csx[i]  = 0.f; d_csc[i]  = 0.f; }
}

__global__ void prep_wfx(const float* __restrict__ W) {
    int j = blockIdx.x, cc = threadIdx.x;
    float wv = W[cc * 512 + j];
    __nv_bfloat16 h = __float2bfloat16(wv);
    d_wfx_h[j * 256 + cc] = h;
    d_wfx_l[j * 256 + cc] = __float2bfloat16(wv - __bfloat162float(h));
}

__global__ void prep_wls(const float* __restrict__ Wx, const float* __restrict__ Wslice,
                         const float* __restrict__ bx, const float* __restrict__ bslice) {
    extern __shared__ float sm[];
    float* ws = sm;
    float* wx = sm + 64;
    int j = blockIdx.x, h = j >> 6, m = j & 63, t = threadIdx.x;
    if (t < 64) ws[t] = Wslice[t * 64 + m];
    for (int i = t; i < 256 * 16; i += 256) {
        int r = i >> 4, q = i & 15;
        *(float4*)&wx[r * 68 + q * 4] = *(const float4*)&Wx[r * 512 + h * 64 + q * 4];
    }
    __syncthreads();
    float acc = 0.f;
#pragma unroll 8
    for (int e = 0; e < 64; e++) acc += wx[t * 68 + e] * ws[e];
    __nv_bfloat16 hh = __float2bfloat16(acc);
    d_wls_h[j * 256 + t] = hh;
    d_wls_l[j * 256 + t] = __float2bfloat16(acc - __bfloat162float(hh));
    if (t == 0) {
        float bb = bslice[m];
        for (int e = 0; e < 64; e++) bb += bx[h * 64 + e] * ws[e];
        d_bls[j] = bb;
    }
}

__global__ void prep_wot() {
    int bc = blockIdx.x;
    int b = bc >> 8, cc = bc & 255, t = threadIdx.x;
    float wv = d_wot[((size_t)b * 512 + t) * 256 + cc];
    __nv_bfloat16 h = __float2bfloat16(wv);
    d_wot_h[(size_t)bc * 512 + t] = h;
    d_wot_l[(size_t)bc * 512 + t] = __float2bfloat16(wv - __bfloat162float(h));
}

// ================= tiny attention + Wo refactor =================
__global__ void attn_kernel(const float* __restrict__ Wq,
                            const float* __restrict__ Wk,
                            const float* __restrict__ Wv) {
    extern __shared__ float sm[];
    float* A  = sm;
    float* Ks = sm + 64 * 65;
    float* Vs = Ks + 64 * 64;
    const int bh = blockIdx.x;
    const int g = threadIdx.x;

    for (int idx = g; idx < 4096; idx += 64) {
        int r = idx >> 6, cc = idx & 63;
        A[r * 65 + cc] = d_tokc[bh * 4096 + idx] / (d_csc[bh * 64 + r] + 1e-5f);
    }
    __syncthreads();
    {
        float ka[64], va[64];
#pragma unroll
        for (int cc = 0; cc < 64; cc++) { ka[cc] = 0.f; va[cc] = 0.f; }
        for (int e = 0; e < 64; e++) {
            float te = A[g * 65 + e];
#pragma unroll
            for (int cc = 0; cc < 64; cc++) {
                ka[cc] += te * Wk[e * 64 + cc];
                va[cc] += te * Wv[e * 64 + cc];
            }
        }
#pragma unroll
        for (int cc = 0; cc < 64; cc++) { Ks[g * 64 + cc] = ka[cc]; Vs[g * 64 + cc] = va[cc]; }
    }
    __syncthreads();
    for (int idx = g; idx < 4096; idx += 64) {
        int r = idx >> 6, cc = idx & 63;
        A[r * 65 + cc] = d_tokx[bh * 4096 + idx] / (d_csx[bh * 64 + r] + 1e-5f);
    }
    __syncthreads();

    float q[64];
#pragma unroll
    for (int cc = 0; cc < 64; cc++) q[cc] = 0.f;
    for (int e = 0; e < 64; e++) {
        float te = A[g * 65 + e];
#pragma unroll
        for (int cc = 0; cc < 64; cc++) q[cc] += te * Wq[e * 64 + cc];
    }
    __syncthreads();
    float* srow = &A[g * 65];
    float mx = -1e30f;
    for (int m = 0; m < 64; m++) {
        float a2 = 0.f;
#pragma unroll
        for (int cc = 0; cc < 64; cc++) a2 += q[cc] * Ks[m * 64 + cc];
        a2 *= 0.125f;
        srow[m] = a2;
        mx = fmaxf(mx, a2);
    }
    float sum = 0.f;
    for (int m = 0; m < 64; m++) { float e = __expf(srow[m] - mx); srow[m] = e; sum += e; }
    float inv = 1.f / sum;
    float o[64];
#pragma unroll
    for (int cc = 0; cc < 64; cc++) o[cc] = 0.f;
    for (int m = 0; m < 64; m++) {
        float p = srow[m] * inv;
#pragma unroll
        for (int cc = 0; cc < 64; cc++) o[cc] += p * Vs[m * 64 + cc];
    }
    float invx = 1.f / (d_csx[bh * 64 + g] + 1e-5f);
#pragma unroll
    for (int cc = 0; cc < 64; cc++) d_outsc[bh * 4096 + g * 64 + cc] = o[cc] * invx;
}

__global__ __launch_bounds__(256) void wot_kernel(const float* __restrict__ Wo) {
    const int bhg = blockIdx.x;
    const int hg = bhg & (H_ * M_ - 1);
    const int h = hg >> 6;
    __shared__ float orow[64];
    const int t = threadIdx.x;
    if (t < 64) orow[t] = d_outsc[bhg * 64 + t];
    __syncthreads();
    float acc = 0.f;
#pragma unroll 8
    for (int cc = 0; cc < 64; cc++) acc += orow[cc] * Wo[(h * 64 + cc) * 256 + t];
    d_wot[(size_t)bhg * 256 + t] = acc;
}

// ================= launcher =================
extern "C" void kernel_launch(void* const* d_in, const int* in_sizes, int n_in,
                              void* d_out, int out_size) {
    const float* x      = (const float*)d_in[0];
    const float* xc     = (const float*)d_in[1];
    const float* Wfx    = (const float*)d_in[2];
    const float* bfx    = (const float*)d_in[3];
    const float* Wx     = (const float*)d_in[4];
    const float* bx     = (const float*)d_in[5];
    const float* Wslice = (const float*)d_in[6];
    const float* bslice = (const float*)d_in[7];
    const float* temp   = (const float*)d_in[8];
    const float* Wq     = (const float*)d_in[9];
    const float* Wk     = (const float*)d_in[10];
    const float* Wv     = (const float*)d_in[11];
    const float* Wo     = (const float*)d_in[12];
    const float* bo     = (const float*)d_in[13];
    float* out = (float*)d_out;

    const int attn_smem = (64 * 65 + 2 * 64 * 64) * (int)sizeof(float);
    const int wls_smem  = (64 + 256 * 68) * (int)sizeof(float);
    cudaFuncSetAttribute(attn_kernel, cudaFuncAttributeMaxDynamicSharedMemorySize, attn_smem);
    cudaFuncSetAttribute(prep_wls,    cudaFuncAttributeMaxDynamicSharedMemorySize, wls_smem);
    cudaFuncSetAttribute(fx_mma,      cudaFuncAttributeMaxDynamicSharedMemorySize, GEMM_SMEM);
    cudaFuncSetAttribute(logit_mma,   cudaFuncAttributeMaxDynamicSharedMemorySize, GEMM_SMEM);
    cudaFuncSetAttribute(final_mma,   cudaFuncAttributeMaxDynamicSharedMemorySize, GEMM_SMEM);
    cudaFuncSetAttribute(token_mma,   cudaFuncAttributeMaxDynamicSharedMemorySize, TOK_SMEM);

    zero_kernel<<<512, 256>>>();
    prep_wfx<<<512, 256>>>(Wfx);
    prep_wls<<<512, 256, wls_smem>>>(Wx, Wslice, bx, bslice);

    dim3 ggrid(4, ROWS_ / 128);
    dim3 tokgrid(16, BH_);
    const int ps_blocks = (int)((size_t)ROWS_ * 256 / 4 / 256);

    // ---- cross pass ----
    presplit_x<<<ps_blocks, 256>>>(xc);
    fx_mma<<<ggrid, 256, GEMM_SMEM>>>(bfx);
    logit_mma<<<ggrid, 256, GEMM_SMEM>>>(temp);
    token_mma<<<tokgrid, 256, TOK_SMEM>>>(0);

    // ---- x pass ----
    presplit_x<<<ps_blocks, 256>>>(x);
    fx_mma<<<ggrid, 256, GEMM_SMEM>>>(bfx);
    logit_mma<<<ggrid, 256, GEMM_SMEM>>>(temp);
    token_mma<<<tokgrid, 256, TOK_SMEM>>>(1);

    // ---- tiny attention + epilogue ----
    attn_kernel<<<BH_, 64, attn_smem>>>(Wq, Wk, Wv);
    wot_kernel<<<B_ * H_ * M_, 256>>>(Wo);
    prep_wot<<<B_ * C_, 512>>>();
    final_mma<<<dim3(2, ROWS_ / 128), 256, GEMM_SMEM>>>(bo, out);
}

// round 7
// speedup vs baseline: 3.3621x; 1.0438x over previous
#include <cuda_runtime.h>
#include <cuda_bf16.h>
#include <cstdint>

#define B_ 4
#define N_ 32768
#define C_ 256
#define H_ 8
#define CH_ 64
#define M_ 64
#define INNER_ 512
#define ROWS_ (B_*N_)          // 131072
#define BH_ 32
#define PASS_SW ((size_t)BH_ * N_ * M_)   // sw elements per pass

// ================= static scratch (2 passes: pass0 = x, pass1 = x_cross) =================
__device__ __nv_bfloat16 d_fx_h[(size_t)2 * ROWS_ * 512];
__device__ __nv_bfloat16 d_fx_l[(size_t)2 * ROWS_ * 512];
__device__ __nv_bfloat16 d_sw_h[(size_t)2 * BH_ * N_ * M_];
__device__ __nv_bfloat16 d_sw_l[(size_t)2 * BH_ * N_ * M_];
__device__ __nv_bfloat16 d_xs_h[(size_t)2 * ROWS_ * 256];
__device__ __nv_bfloat16 d_xs_l[(size_t)2 * ROWS_ * 256];
__device__ float d_tokx[BH_ * M_ * CH_];
__device__ float d_tokc[BH_ * M_ * CH_];
__device__ float d_csx[BH_ * M_];
__device__ float d_csc[BH_ * M_];
__device__ float d_outsc[BH_ * M_ * CH_];
__device__ float d_wot[B_ * INNER_ * C_];
__device__ float d_bls[INNER_];
__device__ __nv_bfloat16 d_wfx_h[INNER_ * C_];
__device__ __nv_bfloat16 d_wfx_l[INNER_ * C_];
__device__ __nv_bfloat16 d_wls_h[INNER_ * C_];
__device__ __nv_bfloat16 d_wls_l[INNER_ * C_];
__device__ __nv_bfloat16 d_wot_h[B_ * C_ * INNER_];
__device__ __nv_bfloat16 d_wot_l[B_ * C_ * INNER_];

// ================= helpers =================
__device__ __forceinline__ uint32_t smem_u32(const void* p) {
    uint32_t a;
    asm("{ .reg .u64 t; cvta.to.shared.u64 t, %1; cvt.u32.u64 %0, t; }" : "=r"(a) : "l"(p));
    return a;
}
__device__ __forceinline__ void ldsm4(uint32_t* r, uint32_t addr) {
    asm volatile("ldmatrix.sync.aligned.m8n8.x4.shared.b16 {%0,%1,%2,%3}, [%4];"
                 : "=r"(r[0]), "=r"(r[1]), "=r"(r[2]), "=r"(r[3]) : "r"(addr));
}
__device__ __forceinline__ void ldsm4t(uint32_t* r, uint32_t addr) {
    asm volatile("ldmatrix.sync.aligned.m8n8.x4.trans.shared.b16 {%0,%1,%2,%3}, [%4];"
                 : "=r"(r[0]), "=r"(r[1]), "=r"(r[2]), "=r"(r[3]) : "r"(addr));
}
__device__ __forceinline__ void mma16816(float* c, const uint32_t* a, const uint32_t* b) {
    asm volatile("mma.sync.aligned.m16n8k16.row.col.f32.bf16.bf16.f32 "
                 "{%0,%1,%2,%3}, {%4,%5,%6,%7}, {%8,%9}, {%0,%1,%2,%3};"
                 : "+f"(c[0]), "+f"(c[1]), "+f"(c[2]), "+f"(c[3])
                 : "r"(a[0]), "r"(a[1]), "r"(a[2]), "r"(a[3]), "r"(b[0]), "r"(b[1]));
}
__device__ __forceinline__ void split2(float x, float y, uint32_t& hi, uint32_t& lo) {
    __nv_bfloat16 hx = __float2bfloat16(x), hy = __float2bfloat16(y);
    float rx = x - __bfloat162float(hx), ry = y - __bfloat162float(hy);
    __nv_bfloat16 lx = __float2bfloat16(rx), ly = __float2bfloat16(ry);
    hi = (uint32_t)__bfloat16_as_ushort(hx) | ((uint32_t)__bfloat16_as_ushort(hy) << 16);
    lo = (uint32_t)__bfloat16_as_ushort(lx) | ((uint32_t)__bfloat16_as_ushort(ly) << 16);
}
__device__ __forceinline__ void cpa16(uint32_t dst, const void* src) {
    asm volatile("cp.async.cg.shared.global [%0], [%1], 16;" :: "r"(dst), "l"(src));
}
#define CP_COMMIT() asm volatile("cp.async.commit_group;" ::: "memory")
#define CP_WAIT1()  asm volatile("cp.async.wait_group 1;" ::: "memory")
#define CP_WAIT2()  asm volatile("cp.async.wait_group 2;" ::: "memory")

#define STAGE_BYTES 32768
#define GEMM_SMEM   98304
#define SWX64(r, byte) ((uint32_t)((r) * 64 + ((byte) ^ ((((r) >> 1) & 3) << 4))))
#define SWX(r, byte) ((uint32_t)((r) * 128 + ((byte) ^ (((r) & 7) << 4))))

#define GEMM_PROLOG() \
    extern __shared__ char smem[]; \
    const uint32_t sb = smem_u32(smem); \
    const int t = threadIdx.x; \
    const int w = t >> 5, lane = t & 31; \
    const int wm = (w & 3) * 32, wn = (w >> 2) * 64; \
    const int g = lane >> 2, tq = lane & 3; \
    const int ar_ = lane & 15, akh_ = lane >> 4; \
    const int qd_ = lane >> 3, bl8_ = lane & 7; \
    uint32_t abase[2], axr[2], bbase[4], bxr[4]; \
    _Pragma("unroll") for (int mi = 0; mi < 2; mi++) { \
        int row = wm + mi * 16 + ar_; \
        abase[mi] = row * 64; axr[mi] = ((row >> 1) & 3) << 4; \
    } \
    _Pragma("unroll") for (int nb = 0; nb < 4; nb++) { \
        int row = wn + nb * 16 + (qd_ >> 1) * 8 + bl8_; \
        bbase[nb] = row * 64; bxr[nb] = ((row >> 1) & 3) << 4; \
    } \
    const uint32_t bk16_ = (qd_ & 1) * 16; \
    const uint32_t ak16_ = akh_ * 16; \
    float c[2][8][4]; \
    _Pragma("unroll") for (int mi = 0; mi < 2; mi++) \
    _Pragma("unroll") for (int ni = 0; ni < 8; ni++) \
    _Pragma("unroll") for (int q = 0; q < 4; q++) c[mi][ni][q] = 0.f;

#define GEMM_COMPUTE_CHUNK32(soff) \
    _Pragma("unroll") for (int ks = 0; ks < 2; ks++) { \
        uint32_t ah[2][4], al[2][4], bh[8][2], bl[8][2]; \
        const uint32_t ka = ks * 32 + ak16_; \
        const uint32_t kb = ks * 32 + bk16_; \
        _Pragma("unroll") for (int mi = 0; mi < 2; mi++) { \
            uint32_t off = (soff) + abase[mi] + (ka ^ axr[mi]); \
            ldsm4(ah[mi], sb + off); \
            ldsm4(al[mi], sb + 8192 + off); \
        } \
        _Pragma("unroll") for (int nb = 0; nb < 4; nb++) { \
            uint32_t off = (soff) + bbase[nb] + (kb ^ bxr[nb]); \
            uint32_t rh[4], rl[4]; \
            ldsm4(rh, sb + 16384 + off); \
            ldsm4(rl, sb + 24576 + off); \
            bh[nb*2][0] = rh[0]; bh[nb*2][1] = rh[1]; \
            bh[nb*2+1][0] = rh[2]; bh[nb*2+1][1] = rh[3]; \
            bl[nb*2][0] = rl[0]; bl[nb*2][1] = rl[1]; \
            bl[nb*2+1][0] = rl[2]; bl[nb*2+1][1] = rl[3]; \
        } \
        _Pragma("unroll") for (int mi = 0; mi < 2; mi++) \
        _Pragma("unroll") for (int ni = 0; ni < 8; ni++) { \
            mma16816(c[mi][ni], ah[mi], bh[ni]); \
            mma16816(c[mi][ni], ah[mi], bl[ni]); \
            mma16816(c[mi][ni], al[mi], bh[ni]); \
        } \
    }

#define ISSUE_K32(Ahp, Alp, Bhp, Blp, m0, j0, k0, s) \
    { \
        uint32_t so = sb + (uint32_t)(s) * STAGE_BYTES; \
        _Pragma("unroll") for (int i = 0; i < 2; i++) { \
            int e = i * 256 + t, r = e >> 2, q = e & 3; \
            uint32_t off = SWX64(r, q * 16); \
            cpa16(so + off,         &(Ahp)[(size_t)((m0) + r) * 256 + (k0) + q * 8]); \
            cpa16(so + 8192 + off,  &(Alp)[(size_t)((m0) + r) * 256 + (k0) + q * 8]); \
            cpa16(so + 16384 + off, &(Bhp)[(size_t)((j0) + r) * 256 + (k0) + q * 8]); \
            cpa16(so + 24576 + off, &(Blp)[(size_t)((j0) + r) * 256 + (k0) + q * 8]); \
        } \
    }

#define PIPELINE3(NC, ISSUE_CH) \
    ISSUE_CH(0, 0); \
    CP_COMMIT(); \
    ISSUE_CH(1, 1); \
    CP_COMMIT(); \
    for (int ch = 0; ch < (NC); ch++) { \
        if (ch + 2 < (NC)) { ISSUE_CH(ch + 2, (ch + 2) % 3); } \
        CP_COMMIT(); \
        CP_WAIT2(); \
        __syncthreads(); \
        GEMM_COMPUTE_CHUNK32((uint32_t)(ch % 3) * STAGE_BYTES); \
        __syncthreads(); \
    }

// ================= fused projection GEMM (fx + logits, both passes) =================
// grid (8, 2048): blockIdx.x<4 -> fx cols, >=4 -> logit cols; rows span 2*ROWS.
__global__ __launch_bounds__(256, 2) void proj_mma(const float* __restrict__ bias,
                                                   const float* __restrict__ temperature) {
    GEMM_PROLOG();
    const int m0 = blockIdx.y * 128;                    // 0..262143
    const bool isfx = blockIdx.x < 4;
    const int j0 = (isfx ? blockIdx.x : blockIdx.x - 4) * 128;
    const __nv_bfloat16* __restrict__ Bh = isfx ? d_wfx_h : d_wls_h;
    const __nv_bfloat16* __restrict__ Bl = isfx ? d_wfx_l : d_wls_l;
#define PJ_ISSUE(ch, s) ISSUE_K32(d_xs_h, d_xs_l, Bh, Bl, m0, j0, (ch) * 32, s)
    PIPELINE3(8, PJ_ISSUE);
#undef PJ_ISSUE
    if (isfx) {
#pragma unroll
        for (int mi = 0; mi < 2; mi++) {
            int row0 = m0 + wm + mi * 16 + g;
#pragma unroll
            for (int ni = 0; ni < 8; ni++) {
                int col = j0 + wn + ni * 8 + tq * 2;
                float2 bb = *(const float2*)&bias[col];
                uint32_t hh, ll;
                split2(c[mi][ni][0] + bb.x, c[mi][ni][1] + bb.y, hh, ll);
                *(uint32_t*)&d_fx_h[(size_t)row0 * 512 + col] = hh;
                *(uint32_t*)&d_fx_l[(size_t)row0 * 512 + col] = ll;
                split2(c[mi][ni][2] + bb.x, c[mi][ni][3] + bb.y, hh, ll);
                *(uint32_t*)&d_fx_h[(size_t)(row0 + 8) * 512 + col] = hh;
                *(uint32_t*)&d_fx_l[(size_t)(row0 + 8) * 512 + col] = ll;
            }
        }
    } else {
        const int h = (j0 >> 6) + (w >> 2);
        float tp = temperature[h];
        tp = fminf(fmaxf(tp, 0.1f), 5.0f);
        const float invt = 1.f / tp;
        float2 blv[8];
#pragma unroll
        for (int ni = 0; ni < 8; ni++)
            blv[ni] = *(const float2*)&d_bls[j0 + wn + ni * 8 + tq * 2];
#pragma unroll
        for (int mi = 0; mi < 2; mi++)
#pragma unroll
            for (int ni = 0; ni < 8; ni++) {
                c[mi][ni][0] = (c[mi][ni][0] + blv[ni].x) * invt;
                c[mi][ni][1] = (c[mi][ni][1] + blv[ni].y) * invt;
                c[mi][ni][2] = (c[mi][ni][2] + blv[ni].x) * invt;
                c[mi][ni][3] = (c[mi][ni][3] + blv[ni].y) * invt;
            }
#pragma unroll
        for (int mi = 0; mi < 2; mi++)
#pragma unroll
            for (int half = 0; half < 2; half++) {
                const int ci = half * 2;
                float mx = -1e30f;
#pragma unroll
                for (int ni = 0; ni < 8; ni++)
                    mx = fmaxf(mx, fmaxf(c[mi][ni][ci], c[mi][ni][ci + 1]));
                mx = fmaxf(mx, __shfl_xor_sync(0xffffffffu, mx, 1));
                mx = fmaxf(mx, __shfl_xor_sync(0xffffffffu, mx, 2));
                float s = 0.f;
#pragma unroll
                for (int ni = 0; ni < 8; ni++) {
                    float e0 = __expf(c[mi][ni][ci] - mx);
                    float e1 = __expf(c[mi][ni][ci + 1] - mx);
                    c[mi][ni][ci] = e0; c[mi][ni][ci + 1] = e1;
                    s += e0 + e1;
                }
                s += __shfl_xor_sync(0xffffffffu, s, 1);
                s += __shfl_xor_sync(0xffffffffu, s, 2);
                float inv = 1.f / s;
                int row = m0 + wm + mi * 16 + half * 8 + g;     // 0..262143
                int pass = row >> 17;
                int rr = row & (ROWS_ - 1);
                int b = rr >> 15, n = rr & (N_ - 1);
                size_t base = (size_t)pass * PASS_SW + ((size_t)(b * H_ + h) * N_ + n) * 64;
#pragma unroll
                for (int ni = 0; ni < 8; ni++) {
                    size_t idx = base + ni * 8 + tq * 2;
                    uint32_t hh, ll;
                    split2(c[mi][ni][ci] * inv, c[mi][ni][ci + 1] * inv, hh, ll);
                    *(uint32_t*)&d_sw_h[idx] = hh;
                    *(uint32_t*)&d_sw_l[idx] = ll;
                }
            }
    }
}

// ================= GEMM 3: out[b] = sw_x[b] (N x 512) @ wot[b] (512 x 256) + bo =================
__global__ __launch_bounds__(256, 2) void final_mma(const float* __restrict__ bo,
                                                    float* __restrict__ out) {
    GEMM_PROLOG();
    const int m0 = blockIdx.y * 128;
    const int j0 = blockIdx.x * 128;
    const int bb_ = m0 >> 15;
    const int n0 = m0 & (N_ - 1);
#define FN_ISSUE(ch, s) \
    { \
        uint32_t so = sb + (uint32_t)(s) * STAGE_BYTES; \
        const int hh_ = (ch) >> 1, g0_ = ((ch) & 1) * 32; \
        const int k0 = (ch) * 32; \
        _Pragma("unroll") for (int i = 0; i < 2; i++) { \
            int e = i * 256 + t, r = e >> 2, q = e & 3; \
            uint32_t off = SWX64(r, q * 16); \
            size_t aidx = ((size_t)(bb_ * H_ + hh_) * N_ + n0 + r) * 64 + g0_ + q * 8; \
            cpa16(so + off,         &d_sw_h[aidx]); \
            cpa16(so + 8192 + off,  &d_sw_l[aidx]); \
            size_t bidx = ((size_t)bb_ * 256 + j0 + r) * 512 + k0 + q * 8; \
            cpa16(so + 16384 + off, &d_wot_h[bidx]); \
            cpa16(so + 24576 + off, &d_wot_l[bidx]); \
        } \
    }
    PIPELINE3(16, FN_ISSUE);
#undef FN_ISSUE
#pragma unroll
    for (int mi = 0; mi < 2; mi++) {
        int row0 = m0 + wm + mi * 16 + g;
#pragma unroll
        for (int ni = 0; ni < 8; ni++) {
            int col = j0 + wn + ni * 8 + tq * 2;
            float2 bbv = *(const float2*)&bo[col];
            float2 o0 = { c[mi][ni][0] + bbv.x, c[mi][ni][1] + bbv.y };
            float2 o1 = { c[mi][ni][2] + bbv.x, c[mi][ni][3] + bbv.y };
            *(float2*)&out[(size_t)row0 * 256 + col] = o0;
            *(float2*)&out[(size_t)(row0 + 8) * 256 + col] = o1;
        }
    }
}

// ================= token aggregation via tensor cores (both passes) =================
// grid (16, 64): blockIdx.y = pass*32 + bh
#define TOK_STAGE 32768
#define TOK_SMEM  65536
__global__ __launch_bounds__(256) void token_mma() {
    extern __shared__ char smem[];
    const uint32_t sb = smem_u32(smem);
    const int by = blockIdx.y;
    const int pass = by >> 5;                 // 0 = x, 1 = x_cross
    const int bh = by & 31;
    float* tok = pass ? d_tokc : d_tokx;
    float* cs  = pass ? d_csc  : d_csx;
    const int b = bh >> 3, h = bh & 7;
    const int n0 = blockIdx.x * 2048;
    const int t = threadIdx.x;
    const int w = t >> 5, lane = t & 31;
    const int wg = (w & 1) * 32;
    const int wc = (w >> 1) * 16;
    const int lg = lane >> 3, l8 = lane & 7;

    const int rowA = (lg >> 1) * 8 + l8;
    uint32_t offA[2];
#pragma unroll
    for (int mi = 0; mi < 2; mi++) {
        int goff = wg + mi * 16 + (lg & 1) * 8;
        offA[mi] = rowA * 128 + ((goff * 2) ^ ((rowA & 7) << 4));
    }
    const int rowB = (lg & 1) * 8 + l8;
    const int coff = wc + (lg >> 1) * 8;
    const uint32_t offB = rowB * 128 + ((coff * 2) ^ ((rowB & 7) << 4));

    const int gcs = t & 63, rq = (t >> 6) * 16;
    float csacc = 0.f;

    float c[2][2][4];
#pragma unroll
    for (int mi = 0; mi < 2; mi++)
#pragma unroll
        for (int ni = 0; ni < 2; ni++)
#pragma unroll
            for (int q = 0; q < 4; q++) c[mi][ni][q] = 0.f;

    const size_t swoff = (size_t)pass * PASS_SW;
    const size_t fxoff = (size_t)pass * ROWS_ * 512;

#define TOK_ISSUE(ch, s) \
    { \
        uint32_t so = sb + (uint32_t)(s) * TOK_STAGE; \
        const int nn = n0 + (ch) * 64; \
        _Pragma("unroll") for (int i = 0; i < 2; i++) { \
            int e = i * 256 + t, r = e >> 3, q = e & 7; \
            uint32_t off = SWX(r, q * 16); \
            size_t sidx = swoff + ((size_t)bh * N_ + nn + r) * 64 + q * 8; \
            cpa16(so + off,         &d_sw_h[sidx]); \
            cpa16(so + 8192 + off,  &d_sw_l[sidx]); \
            size_t fidx = fxoff + ((size_t)(b * N_ + nn + r)) * 512 + h * 64 + q * 8; \
            cpa16(so + 16384 + off, &d_fx_h[fidx]); \
            cpa16(so + 24576 + off, &d_fx_l[fidx]); \
        } \
    }

    TOK_ISSUE(0, 0);
    CP_COMMIT();
    for (int ch = 0; ch < 32; ch++) {
        if (ch + 1 < 32) { TOK_ISSUE(ch + 1, (ch + 1) & 1); }
        CP_COMMIT();
        CP_WAIT1();
        __syncthreads();
        const uint32_t so = (uint32_t)(ch & 1) * TOK_STAGE;
#pragma unroll
        for (int ks = 0; ks < 4; ks++) {
            const uint32_t kso = so + ks * 2048;
            uint32_t ah[2][4], al[2][4], rbh[4], rbl[4];
#pragma unroll
            for (int mi = 0; mi < 2; mi++) {
                ldsm4t(ah[mi], sb + kso + offA[mi]);
                ldsm4t(al[mi], sb + 8192 + kso + offA[mi]);
            }
            ldsm4t(rbh, sb + 16384 + kso + offB);
            ldsm4t(rbl, sb + 24576 + kso + offB);
            uint32_t bfh[2][2] = {{rbh[0], rbh[1]}, {rbh[2], rbh[3]}};
            uint32_t bfl[2][2] = {{rbl[0], rbl[1]}, {rbl[2], rbl[3]}};
#pragma unroll
            for (int mi = 0; mi < 2; mi++)
#pragma unroll
                for (int ni = 0; ni < 2; ni++) {
                    mma16816(c[mi][ni], ah[mi], bfh[ni]);
                    mma16816(c[mi][ni], ah[mi], bfl[ni]);
                    mma16816(c[mi][ni], al[mi], bfh[ni]);
                }
        }
#pragma unroll
        for (int r = 0; r < 16; r++) {
            int rr = rq + r;
            uint32_t off = so + rr * 128 + (((uint32_t)(gcs * 2)) ^ (((uint32_t)(rr & 7)) << 4));
            float vh = __bfloat162float(*(const __nv_bfloat16*)(smem + off));
            float vl = __bfloat162float(*(const __nv_bfloat16*)(smem + 8192 + off));
            csacc += vh + vl;
        }
        __syncthreads();
    }
#undef TOK_ISSUE
    const int grow = lane >> 2, cpair = (lane & 3) * 2;
#pragma unroll
    for (int mi = 0; mi < 2; mi++) {
        int gg = wg + mi * 16 + grow;
#pragma unroll
        for (int ni = 0; ni < 2; ni++) {
            int col = wc + ni * 8 + cpair;
            atomicAdd(&tok[bh * 4096 + gg * 64 + col],       c[mi][ni][0]);
            atomicAdd(&tok[bh * 4096 + gg * 64 + col + 1],   c[mi][ni][1]);
            atomicAdd(&tok[bh * 4096 + (gg + 8) * 64 + col],     c[mi][ni][2]);
            atomicAdd(&tok[bh * 4096 + (gg + 8) * 64 + col + 1], c[mi][ni][3]);
        }
    }
    atomicAdd(&cs[bh * 64 + gcs], csacc);
}

// ================= prep kernels =================
// both inputs in one launch: blocks [0,32768) -> x (pass0), [32768,65536) -> xc (pass1)
__global__ void presplit2(const float* __restrict__ X0, const float* __restrict__ X1) {
    const int blk = blockIdx.x;
    const float* X = (blk < 32768) ? X0 : X1;
    size_t li = (size_t)(blk & 32767) * 256 + threadIdx.x;       // float4 index in input
    size_t gi = (size_t)blk * 256 + threadIdx.x;                 // float4 index in output
    float4 v = ((const float4*)X)[li];
    uint2 hh, ll;
    split2(v.x, v.y, hh.x, ll.x);
    split2(v.z, v.w, hh.y, ll.y);
    ((uint2*)d_xs_h)[gi] = hh;
    ((uint2*)d_xs_l)[gi] = ll;
}

__global__ void zero_kernel() {
    int i = blockIdx.x * blockDim.x + threadIdx.x;
    if (i < BH_ * M_ * CH_) { d_tokx[i] = 0.f; d_tokc[i] = 0.f; }
    if (i < BH_ * M_)       { d_csx[i]  = 0.f; d_csc[i]  = 0.f; }
}

__global__ void prep_wfx(const float* __restrict__ W) {
    int j = blockIdx.x, cc = threadIdx.x;
    float wv = W[cc * 512 + j];
    __nv_bfloat16 h = __float2bfloat16(wv);
    d_wfx_h[j * 256 + cc] = h;
    d_wfx_l[j * 256 + cc] = __float2bfloat16(wv - __bfloat162float(h));
}

__global__ void prep_wls(const float* __restrict__ Wx, const float* __restrict__ Wslice,
                         const float* __restrict__ bx, const float* __restrict__ bslice) {
    extern __shared__ float sm[];
    float* ws = sm;
    float* wx = sm + 64;
    int j = blockIdx.x, h = j >> 6, m = j & 63, t = threadIdx.x;
    if (t < 64) ws[t] = Wslice[t * 64 + m];
    for (int i = t; i < 256 * 16; i += 256) {
        int r = i >> 4, q = i & 15;
        *(float4*)&wx[r * 68 + q * 4] = *(const float4*)&Wx[r * 512 + h * 64 + q * 4];
    }
    __syncthreads();
    float acc = 0.f;
#pragma unroll 8
    for (int e = 0; e < 64; e++) acc += wx[t * 68 + e] * ws[e];
    __nv_bfloat16 hh = __float2bfloat16(acc);
    d_wls_h[j * 256 + t] = hh;
    d_wls_l[j * 256 + t] = __float2bfloat16(acc - __bfloat162float(hh));
    if (t == 0) {
        float bb = bslice[m];
        for (int e = 0; e < 64; e++) bb += bx[h * 64 + e] * ws[e];
        d_bls[j] = bb;
    }
}

__global__ void prep_wot() {
    int bc = blockIdx.x;
    int b = bc >> 8, cc = bc & 255, t = threadIdx.x;
    float wv = d_wot[((size_t)b * 512 + t) * 256 + cc];
    __nv_bfloat16 h = __float2bfloat16(wv);
    d_wot_h[(size_t)bc * 512 + t] = h;
    d_wot_l[(size_t)bc * 512 + t] = __float2bfloat16(wv - __bfloat162float(h));
}

// ================= tiny attention + Wo refactor =================
__global__ void attn_kernel(const float* __restrict__ Wq,
                            const float* __restrict__ Wk,
                            const float* __restrict__ Wv) {
    extern __shared__ float sm[];
    float* A  = sm;
    float* Ks = sm + 64 * 65;
    float* Vs = Ks + 64 * 64;
    const int bh = blockIdx.x;
    const int g = threadIdx.x;

    for (int idx = g; idx < 4096; idx += 64) {
        int r = idx >> 6, cc = idx & 63;
        A[r * 65 + cc] = d_tokc[bh * 4096 + idx] / (d_csc[bh * 64 + r] + 1e-5f);
    }
    __syncthreads();
    {
        float ka[64], va[64];
#pragma unroll
        for (int cc = 0; cc < 64; cc++) { ka[cc] = 0.f; va[cc] = 0.f; }
        for (int e = 0; e < 64; e++) {
            float te = A[g * 65 + e];
#pragma unroll
            for (int cc = 0; cc < 64; cc++) {
                ka[cc] += te * Wk[e * 64 + cc];
                va[cc] += te * Wv[e * 64 + cc];
            }
        }
#pragma unroll
        for (int cc = 0; cc < 64; cc++) { Ks[g * 64 + cc] = ka[cc]; Vs[g * 64 + cc] = va[cc]; }
    }
    __syncthreads();
    for (int idx = g; idx < 4096; idx += 64) {
        int r = idx >> 6, cc = idx & 63;
        A[r * 65 + cc] = d_tokx[bh * 4096 + idx] / (d_csx[bh * 64 + r] + 1e-5f);
    }
    __syncthreads();

    float q[64];
#pragma unroll
    for (int cc = 0; cc < 64; cc++) q[cc] = 0.f;
    for (int e = 0; e < 64; e++) {
        float te = A[g * 65 + e];
#pragma unroll
        for (int cc = 0; cc < 64; cc++) q[cc] += te * Wq[e * 64 + cc];
    }
    __syncthreads();
    float* srow = &A[g * 65];
    float mx = -1e30f;
    for (int m = 0; m < 64; m++) {
        float a2 = 0.f;
#pragma unroll
        for (int cc = 0; cc < 64; cc++) a2 += q[cc] * Ks[m * 64 + cc];
        a2 *= 0.125f;
        srow[m] = a2;
        mx = fmaxf(mx, a2);
    }
    float sum = 0.f;
    for (int m = 0; m < 64; m++) { float e = __expf(srow[m] - mx); srow[m] = e; sum += e; }
    float inv = 1.f / sum;
    float o[64];
#pragma unroll
    for (int cc = 0; cc < 64; cc++) o[cc] = 0.f;
    for (int m = 0; m < 64; m++) {
        float p = srow[m] * inv;
#pragma unroll
        for (int cc = 0; cc < 64; cc++) o[cc] += p * Vs[m * 64 + cc];
    }
    float invx = 1.f / (d_csx[bh * 64 + g] + 1e-5f);
#pragma unroll
    for (int cc = 0; cc < 64; cc++) d_outsc[bh * 4096 + g * 64 + cc] = o[cc] * invx;
}

__global__ __launch_bounds__(256) void wot_kernel(const float* __restrict__ Wo) {
    const int bhg = blockIdx.x;
    const int hg = bhg & (H_ * M_ - 1);
    const int h = hg >> 6;
    __shared__ float orow[64];
    const int t = threadIdx.x;
    if (t < 64) orow[t] = d_outsc[bhg * 64 + t];
    __syncthreads();
    float acc = 0.f;
#pragma unroll 8
    for (int cc = 0; cc < 64; cc++) acc += orow[cc] * Wo[(h * 64 + cc) * 256 + t];
    d_wot[(size_t)bhg * 256 + t] = acc;
}

// ================= launcher =================
extern "C" void kernel_launch(void* const* d_in, const int* in_sizes, int n_in,
                              void* d_out, int out_size) {
    const float* x      = (const float*)d_in[0];
    const float* xc     = (const float*)d_in[1];
    const float* Wfx    = (const float*)d_in[2];
    const float* bfx    = (const float*)d_in[3];
    const float* Wx     = (const float*)d_in[4];
    const float* bx     = (const float*)d_in[5];
    const float* Wslice = (const float*)d_in[6];
    const float* bslice = (const float*)d_in[7];
    const float* temp   = (const float*)d_in[8];
    const float* Wq     = (const float*)d_in[9];
    const float* Wk     = (const float*)d_in[10];
    const float* Wv     = (const float*)d_in[11];
    const float* Wo     = (const float*)d_in[12];
    const float* bo     = (const float*)d_in[13];
    float* out = (float*)d_out;

    const int attn_smem = (64 * 65 + 2 * 64 * 64) * (int)sizeof(float);
    const int wls_smem  = (64 + 256 * 68) * (int)sizeof(float);
    cudaFuncSetAttribute(attn_kernel, cudaFuncAttributeMaxDynamicSharedMemorySize, attn_smem);
    cudaFuncSetAttribute(prep_wls,    cudaFuncAttributeMaxDynamicSharedMemorySize, wls_smem);
    cudaFuncSetAttribute(proj_mma,    cudaFuncAttributeMaxDynamicSharedMemorySize, GEMM_SMEM);
    cudaFuncSetAttribute(final_mma,   cudaFuncAttributeMaxDynamicSharedMemorySize, GEMM_SMEM);
    cudaFuncSetAttribute(token_mma,   cudaFuncAttributeMaxDynamicSharedMemorySize, TOK_SMEM);

    zero_kernel<<<512, 256>>>();
    prep_wfx<<<512, 256>>>(Wfx);
    prep_wls<<<512, 256, wls_smem>>>(Wx, Wslice, bx, bslice);

    presplit2<<<65536, 256>>>(x, xc);
    proj_mma<<<dim3(8, 2 * ROWS_ / 128), 256, GEMM_SMEM>>>(bfx, temp);
    token_mma<<<dim3(16, 64), 256, TOK_SMEM>>>();

    attn_kernel<<<BH_, 64, attn_smem>>>(Wq, Wk, Wv);
    wot_kernel<<<B_ * H_ * M_, 256>>>(Wo);
    prep_wot<<<B_ * C_, 512>>>();
    final_mma<<<dim3(2, ROWS_ / 128), 256, GEMM_SMEM>>>(bo, out);
}

// round 8
// speedup vs baseline: 3.4883x; 1.0375x over previous
#include <cuda_runtime.h>
#include <cuda_bf16.h>
#include <cstdint>

#define B_ 4
#define N_ 32768
#define C_ 256
#define H_ 8
#define CH_ 64
#define M_ 64
#define INNER_ 512
#define ROWS_ (B_*N_)          // 131072
#define BH_ 32
#define PASS_SW ((size_t)BH_ * N_ * M_)

// ================= static scratch (2 passes: pass0 = x, pass1 = x_cross) =================
__device__ __nv_bfloat16 d_fx_h[(size_t)2 * ROWS_ * 512];
__device__ __nv_bfloat16 d_fx_l[(size_t)2 * ROWS_ * 512];
__device__ __nv_bfloat16 d_sw_h[(size_t)2 * BH_ * N_ * M_];
__device__ __nv_bfloat16 d_sw_l[(size_t)2 * BH_ * N_ * M_];
__device__ __nv_bfloat16 d_xs_h[(size_t)2 * ROWS_ * 256];
__device__ __nv_bfloat16 d_xs_l[(size_t)2 * ROWS_ * 256];
__device__ float d_tokx[BH_ * M_ * CH_];
__device__ float d_tokc[BH_ * M_ * CH_];
__device__ float d_csx[BH_ * M_];
__device__ float d_csc[BH_ * M_];
__device__ float d_outsc[BH_ * M_ * CH_];
__device__ float d_bls[INNER_];
__device__ __nv_bfloat16 d_wfx_h[INNER_ * C_];
__device__ __nv_bfloat16 d_wfx_l[INNER_ * C_];
__device__ __nv_bfloat16 d_wls_h[INNER_ * C_];
__device__ __nv_bfloat16 d_wls_l[INNER_ * C_];
__device__ __nv_bfloat16 d_wot_h[B_ * C_ * INNER_];
__device__ __nv_bfloat16 d_wot_l[B_ * C_ * INNER_];

// ================= helpers =================
__device__ __forceinline__ uint32_t smem_u32(const void* p) {
    uint32_t a;
    asm("{ .reg .u64 t; cvta.to.shared.u64 t, %1; cvt.u32.u64 %0, t; }" : "=r"(a) : "l"(p));
    return a;
}
__device__ __forceinline__ void ldsm4(uint32_t* r, uint32_t addr) {
    asm volatile("ldmatrix.sync.aligned.m8n8.x4.shared.b16 {%0,%1,%2,%3}, [%4];"
                 : "=r"(r[0]), "=r"(r[1]), "=r"(r[2]), "=r"(r[3]) : "r"(addr));
}
__device__ __forceinline__ void ldsm4t(uint32_t* r, uint32_t addr) {
    asm volatile("ldmatrix.sync.aligned.m8n8.x4.trans.shared.b16 {%0,%1,%2,%3}, [%4];"
                 : "=r"(r[0]), "=r"(r[1]), "=r"(r[2]), "=r"(r[3]) : "r"(addr));
}
__device__ __forceinline__ void mma16816(float* c, const uint32_t* a, const uint32_t* b) {
    asm volatile("mma.sync.aligned.m16n8k16.row.col.f32.bf16.bf16.f32 "
                 "{%0,%1,%2,%3}, {%4,%5,%6,%7}, {%8,%9}, {%0,%1,%2,%3};"
                 : "+f"(c[0]), "+f"(c[1]), "+f"(c[2]), "+f"(c[3])
                 : "r"(a[0]), "r"(a[1]), "r"(a[2]), "r"(a[3]), "r"(b[0]), "r"(b[1]));
}
__device__ __forceinline__ void split2(float x, float y, uint32_t& hi, uint32_t& lo) {
    __nv_bfloat16 hx = __float2bfloat16(x), hy = __float2bfloat16(y);
    float rx = x - __bfloat162float(hx), ry = y - __bfloat162float(hy);
    __nv_bfloat16 lx = __float2bfloat16(rx), ly = __float2bfloat16(ry);
    hi = (uint32_t)__bfloat16_as_ushort(hx) | ((uint32_t)__bfloat16_as_ushort(hy) << 16);
    lo = (uint32_t)__bfloat16_as_ushort(lx) | ((uint32_t)__bfloat16_as_ushort(ly) << 16);
}
__device__ __forceinline__ void cpa16(uint32_t dst, const void* src) {
    asm volatile("cp.async.cg.shared.global [%0], [%1], 16;" :: "r"(dst), "l"(src));
}
#define CP_COMMIT() asm volatile("cp.async.commit_group;" ::: "memory")
#define CP_WAIT1()  asm volatile("cp.async.wait_group 1;" ::: "memory")

#define STAGE_BYTES 32768
#define GEMM_SMEM   98304
#define SWX64(r, byte) ((uint32_t)((r) * 64 + ((byte) ^ ((((r) >> 1) & 3) << 4))))
#define SWX(r, byte) ((uint32_t)((r) * 128 + ((byte) ^ (((r) & 7) << 4))))

#define GEMM_PROLOG() \
    extern __shared__ char smem[]; \
    const uint32_t sb = smem_u32(smem); \
    const int t = threadIdx.x; \
    const int w = t >> 5, lane = t & 31; \
    const int wm = (w & 3) * 32, wn = (w >> 2) * 64; \
    const int g = lane >> 2, tq = lane & 3; \
    const int ar_ = lane & 15, akh_ = lane >> 4; \
    const int qd_ = lane >> 3, bl8_ = lane & 7; \
    uint32_t abase[2], axr[2], bbase[4], bxr[4]; \
    _Pragma("unroll") for (int mi = 0; mi < 2; mi++) { \
        int row = wm + mi * 16 + ar_; \
        abase[mi] = row * 64; axr[mi] = ((row >> 1) & 3) << 4; \
    } \
    _Pragma("unroll") for (int nb = 0; nb < 4; nb++) { \
        int row = wn + nb * 16 + (qd_ >> 1) * 8 + bl8_; \
        bbase[nb] = row * 64; bxr[nb] = ((row >> 1) & 3) << 4; \
    } \
    const uint32_t bk16_ = (qd_ & 1) * 16; \
    const uint32_t ak16_ = akh_ * 16; \
    float c[2][8][4]; \
    _Pragma("unroll") for (int mi = 0; mi < 2; mi++) \
    _Pragma("unroll") for (int ni = 0; ni < 8; ni++) \
    _Pragma("unroll") for (int q = 0; q < 4; q++) c[mi][ni][q] = 0.f;

#define GEMM_COMPUTE_CHUNK32(soff) \
    _Pragma("unroll") for (int ks = 0; ks < 2; ks++) { \
        uint32_t ah[2][4], al[2][4], bh[8][2], bl[8][2]; \
        const uint32_t ka = ks * 32 + ak16_; \
        const uint32_t kb = ks * 32 + bk16_; \
        _Pragma("unroll") for (int mi = 0; mi < 2; mi++) { \
            uint32_t off = (soff) + abase[mi] + (ka ^ axr[mi]); \
            ldsm4(ah[mi], sb + off); \
            ldsm4(al[mi], sb + 8192 + off); \
        } \
        _Pragma("unroll") for (int nb = 0; nb < 4; nb++) { \
            uint32_t off = (soff) + bbase[nb] + (kb ^ bxr[nb]); \
            uint32_t rh[4], rl[4]; \
            ldsm4(rh, sb + 16384 + off); \
            ldsm4(rl, sb + 24576 + off); \
            bh[nb*2][0] = rh[0]; bh[nb*2][1] = rh[1]; \
            bh[nb*2+1][0] = rh[2]; bh[nb*2+1][1] = rh[3]; \
            bl[nb*2][0] = rl[0]; bl[nb*2][1] = rl[1]; \
            bl[nb*2+1][0] = rl[2]; bl[nb*2+1][1] = rl[3]; \
        } \
        _Pragma("unroll") for (int mi = 0; mi < 2; mi++) \
        _Pragma("unroll") for (int ni = 0; ni < 8; ni++) { \
            mma16816(c[mi][ni], ah[mi], bh[ni]); \
            mma16816(c[mi][ni], ah[mi], bl[ni]); \
            mma16816(c[mi][ni], al[mi], bh[ni]); \
        } \
    }

#define ISSUE_K32(Ahp, Alp, Bhp, Blp, m0, j0, k0, s) \
    { \
        uint32_t so = sb + (uint32_t)(s) * STAGE_BYTES; \
        _Pragma("unroll") for (int i = 0; i < 2; i++) { \
            int e = i * 256 + t, r = e >> 2, q = e & 3; \
            uint32_t off = SWX64(r, q * 16); \
            cpa16(so + off,         &(Ahp)[(size_t)((m0) + r) * 256 + (k0) + q * 8]); \
            cpa16(so + 8192 + off,  &(Alp)[(size_t)((m0) + r) * 256 + (k0) + q * 8]); \
            cpa16(so + 16384 + off, &(Bhp)[(size_t)((j0) + r) * 256 + (k0) + q * 8]); \
            cpa16(so + 24576 + off, &(Blp)[(size_t)((j0) + r) * 256 + (k0) + q * 8]); \
        } \
    }

// single-barrier 3-stage pipeline: wait -> bar -> compute(ch) -> issue(ch+2) -> commit.
// Overwrite of stage (ch+2)%3 == (ch-1)%3 is safe: every warp passed this
// iteration's barrier only after finishing compute(ch-1). Always-commit keeps
// wait_group 1 exact through the drain iterations.
#define PIPELINE3(NC, ISSUE_CH) \
    ISSUE_CH(0, 0); \
    CP_COMMIT(); \
    ISSUE_CH(1, 1); \
    CP_COMMIT(); \
    for (int ch = 0; ch < (NC); ch++) { \
        CP_WAIT1(); \
        __syncthreads(); \
        GEMM_COMPUTE_CHUNK32((uint32_t)(ch % 3) * STAGE_BYTES); \
        if (ch + 2 < (NC)) { ISSUE_CH(ch + 2, (ch + 2) % 3); } \
        CP_COMMIT(); \
    }

// ================= fused projection GEMM (fx + logits, both passes) =================
__global__ __launch_bounds__(256, 2) void proj_mma(const float* __restrict__ bias,
                                                   const float* __restrict__ temperature) {
    GEMM_PROLOG();
    const int m0 = blockIdx.y * 128;
    const bool isfx = blockIdx.x < 4;
    const int j0 = (isfx ? blockIdx.x : blockIdx.x - 4) * 128;
    const __nv_bfloat16* __restrict__ Bh = isfx ? d_wfx_h : d_wls_h;
    const __nv_bfloat16* __restrict__ Bl = isfx ? d_wfx_l : d_wls_l;
#define PJ_ISSUE(ch, s) ISSUE_K32(d_xs_h, d_xs_l, Bh, Bl, m0, j0, (ch) * 32, s)
    PIPELINE3(8, PJ_ISSUE);
#undef PJ_ISSUE
    if (isfx) {
#pragma unroll
        for (int mi = 0; mi < 2; mi++) {
            int row0 = m0 + wm + mi * 16 + g;
#pragma unroll
            for (int ni = 0; ni < 8; ni++) {
                int col = j0 + wn + ni * 8 + tq * 2;
                float2 bb = *(const float2*)&bias[col];
                uint32_t hh, ll;
                split2(c[mi][ni][0] + bb.x, c[mi][ni][1] + bb.y, hh, ll);
                *(uint32_t*)&d_fx_h[(size_t)row0 * 512 + col] = hh;
                *(uint32_t*)&d_fx_l[(size_t)row0 * 512 + col] = ll;
                split2(c[mi][ni][2] + bb.x, c[mi][ni][3] + bb.y, hh, ll);
                *(uint32_t*)&d_fx_h[(size_t)(row0 + 8) * 512 + col] = hh;
                *(uint32_t*)&d_fx_l[(size_t)(row0 + 8) * 512 + col] = ll;
            }
        }
    } else {
        const int h = (j0 >> 6) + (w >> 2);
        float tp = temperature[h];
        tp = fminf(fmaxf(tp, 0.1f), 5.0f);
        const float invt = 1.f / tp;
        float2 blv[8];
#pragma unroll
        for (int ni = 0; ni < 8; ni++)
            blv[ni] = *(const float2*)&d_bls[j0 + wn + ni * 8 + tq * 2];
#pragma unroll
        for (int mi = 0; mi < 2; mi++)
#pragma unroll
            for (int ni = 0; ni < 8; ni++) {
                c[mi][ni][0] = (c[mi][ni][0] + blv[ni].x) * invt;
                c[mi][ni][1] = (c[mi][ni][1] + blv[ni].y) * invt;
                c[mi][ni][2] = (c[mi][ni][2] + blv[ni].x) * invt;
                c[mi][ni][3] = (c[mi][ni][3] + blv[ni].y) * invt;
            }
#pragma unroll
        for (int mi = 0; mi < 2; mi++)
#pragma unroll
            for (int half = 0; half < 2; half++) {
                const int ci = half * 2;
                float mx = -1e30f;
#pragma unroll
                for (int ni = 0; ni < 8; ni++)
                    mx = fmaxf(mx, fmaxf(c[mi][ni][ci], c[mi][ni][ci + 1]));
                mx = fmaxf(mx, __shfl_xor_sync(0xffffffffu, mx, 1));
                mx = fmaxf(mx, __shfl_xor_sync(0xffffffffu, mx, 2));
                float s = 0.f;
#pragma unroll
                for (int ni = 0; ni < 8; ni++) {
                    float e0 = __expf(c[mi][ni][ci] - mx);
                    float e1 = __expf(c[mi][ni][ci + 1] - mx);
                    c[mi][ni][ci] = e0; c[mi][ni][ci + 1] = e1;
                    s += e0 + e1;
                }
                s += __shfl_xor_sync(0xffffffffu, s, 1);
                s += __shfl_xor_sync(0xffffffffu, s, 2);
                float inv = 1.f / s;
                int row = m0 + wm + mi * 16 + half * 8 + g;
                int pass = row >> 17;
                int rr = row & (ROWS_ - 1);
                int b = rr >> 15, n = rr & (N_ - 1);
                size_t base = (size_t)pass * PASS_SW + ((size_t)(b * H_ + h) * N_ + n) * 64;
#pragma unroll
                for (int ni = 0; ni < 8; ni++) {
                    size_t idx = base + ni * 8 + tq * 2;
                    uint32_t hh, ll;
                    split2(c[mi][ni][ci] * inv, c[mi][ni][ci + 1] * inv, hh, ll);
                    *(uint32_t*)&d_sw_h[idx] = hh;
                    *(uint32_t*)&d_sw_l[idx] = ll;
                }
            }
    }
}

// ================= GEMM 3: out[b] = sw_x[b] (N x 512) @ wot[b] (512 x 256) + bo =================
__global__ __launch_bounds__(256, 2) void final_mma(const float* __restrict__ bo,
                                                    float* __restrict__ out) {
    GEMM_PROLOG();
    const int m0 = blockIdx.y * 128;
    const int j0 = blockIdx.x * 128;
    const int bb_ = m0 >> 15;
    const int n0 = m0 & (N_ - 1);
#define FN_ISSUE(ch, s) \
    { \
        uint32_t so = sb + (uint32_t)(s) * STAGE_BYTES; \
        const int hh_ = (ch) >> 1, g0_ = ((ch) & 1) * 32; \
        const int k0 = (ch) * 32; \
        _Pragma("unroll") for (int i = 0; i < 2; i++) { \
            int e = i * 256 + t, r = e >> 2, q = e & 3; \
            uint32_t off = SWX64(r, q * 16); \
            size_t aidx = ((size_t)(bb_ * H_ + hh_) * N_ + n0 + r) * 64 + g0_ + q * 8; \
            cpa16(so + off,         &d_sw_h[aidx]); \
            cpa16(so + 8192 + off,  &d_sw_l[aidx]); \
            size_t bidx = ((size_t)bb_ * 256 + j0 + r) * 512 + k0 + q * 8; \
            cpa16(so + 16384 + off, &d_wot_h[bidx]); \
            cpa16(so + 24576 + off, &d_wot_l[bidx]); \
        } \
    }
    PIPELINE3(16, FN_ISSUE);
#undef FN_ISSUE
#pragma unroll
    for (int mi = 0; mi < 2; mi++) {
        int row0 = m0 + wm + mi * 16 + g;
#pragma unroll
        for (int ni = 0; ni < 8; ni++) {
            int col = j0 + wn + ni * 8 + tq * 2;
            float2 bbv = *(const float2*)&bo[col];
            float2 o0 = { c[mi][ni][0] + bbv.x, c[mi][ni][1] + bbv.y };
            float2 o1 = { c[mi][ni][2] + bbv.x, c[mi][ni][3] + bbv.y };
            *(float2*)&out[(size_t)row0 * 256 + col] = o0;
            *(float2*)&out[(size_t)(row0 + 8) * 256 + col] = o1;
        }
    }
}

// ================= token aggregation via tensor cores (both passes) =================
// 3 stages x 32KB, single barrier per chunk
#define TOK_STAGE 32768
#define TOK_SMEM  98304
__global__ __launch_bounds__(256, 2) void token_mma() {
    extern __shared__ char smem[];
    const uint32_t sb = smem_u32(smem);
    const int by = blockIdx.y;
    const int pass = by >> 5;
    const int bh = by & 31;
    float* tok = pass ? d_tokc : d_tokx;
    float* cs  = pass ? d_csc  : d_csx;
    const int b = bh >> 3, h = bh & 7;
    const int n0 = blockIdx.x * 2048;
    const int t = threadIdx.x;
    const int w = t >> 5, lane = t & 31;
    const int wg = (w & 1) * 32;
    const int wc = (w >> 1) * 16;
    const int lg = lane >> 3, l8 = lane & 7;

    const int rowA = (lg >> 1) * 8 + l8;
    uint32_t offA[2];
#pragma unroll
    for (int mi = 0; mi < 2; mi++) {
        int goff = wg + mi * 16 + (lg & 1) * 8;
        offA[mi] = rowA * 128 + ((goff * 2) ^ ((rowA & 7) << 4));
    }
    const int rowB = (lg & 1) * 8 + l8;
    const int coff = wc + (lg >> 1) * 8;
    const uint32_t offB = rowB * 128 + ((coff * 2) ^ ((rowB & 7) << 4));

    const int gcs = t & 63, rq = (t >> 6) * 16;
    float csacc = 0.f;

    float c[2][2][4];
#pragma unroll
    for (int mi = 0; mi < 2; mi++)
#pragma unroll
        for (int ni = 0; ni < 2; ni++)
#pragma unroll
            for (int q = 0; q < 4; q++) c[mi][ni][q] = 0.f;

    const size_t swoff = (size_t)pass * PASS_SW;
    const size_t fxoff = (size_t)pass * ROWS_ * 512;

#define TOK_ISSUE(ch, s) \
    { \
        uint32_t so = sb + (uint32_t)(s) * TOK_STAGE; \
        const int nn = n0 + (ch) * 64; \
        _Pragma("unroll") for (int i = 0; i < 2; i++) { \
            int e = i * 256 + t, r = e >> 3, q = e & 7; \
            uint32_t off = SWX(r, q * 16); \
            size_t sidx = swoff + ((size_t)bh * N_ + nn + r) * 64 + q * 8; \
            cpa16(so + off,         &d_sw_h[sidx]); \
            cpa16(so + 8192 + off,  &d_sw_l[sidx]); \
            size_t fidx = fxoff + ((size_t)(b * N_ + nn + r)) * 512 + h * 64 + q * 8; \
            cpa16(so + 16384 + off, &d_fx_h[fidx]); \
            cpa16(so + 24576 + off, &d_fx_l[fidx]); \
        } \
    }

    TOK_ISSUE(0, 0);
    CP_COMMIT();
    TOK_ISSUE(1, 1);
    CP_COMMIT();
    for (int ch = 0; ch < 32; ch++) {
        CP_WAIT1();
        __syncthreads();
        const uint32_t so = (uint32_t)(ch % 3) * TOK_STAGE;
#pragma unroll
        for (int ks = 0; ks < 4; ks++) {
            const uint32_t kso = so + ks * 2048;
            uint32_t ah[2][4], al[2][4], rbh[4], rbl[4];
#pragma unroll
            for (int mi = 0; mi < 2; mi++) {
                ldsm4t(ah[mi], sb + kso + offA[mi]);
                ldsm4t(al[mi], sb + 8192 + kso + offA[mi]);
            }
            ldsm4t(rbh, sb + 16384 + kso + offB);
            ldsm4t(rbl, sb + 24576 + kso + offB);
            uint32_t bfh[2][2] = {{rbh[0], rbh[1]}, {rbh[2], rbh[3]}};
            uint32_t bfl[2][2] = {{rbl[0], rbl[1]}, {rbl[2], rbl[3]}};
#pragma unroll
            for (int mi = 0; mi < 2; mi++)
#pragma unroll
                for (int ni = 0; ni < 2; ni++) {
                    mma16816(c[mi][ni], ah[mi], bfh[ni]);
                    mma16816(c[mi][ni], ah[mi], bfl[ni]);
                    mma16816(c[mi][ni], al[mi], bfh[ni]);
                }
        }
#pragma unroll
        for (int r = 0; r < 16; r++) {
            int rr = rq + r;
            uint32_t off = so + rr * 128 + (((uint32_t)(gcs * 2)) ^ (((uint32_t)(rr & 7)) << 4));
            float vh = __bfloat162float(*(const __nv_bfloat16*)(smem + off));
            float vl = __bfloat162float(*(const __nv_bfloat16*)(smem + 8192 + off));
            csacc += vh + vl;
        }
        if (ch + 2 < 32) { TOK_ISSUE(ch + 2, (ch + 2) % 3); }
        CP_COMMIT();
    }
#undef TOK_ISSUE
    const int grow = lane >> 2, cpair = (lane & 3) * 2;
#pragma unroll
    for (int mi = 0; mi < 2; mi++) {
        int gg = wg + mi * 16 + grow;
#pragma unroll
        for (int ni = 0; ni < 2; ni++) {
            int col = wc + ni * 8 + cpair;
            atomicAdd(&tok[bh * 4096 + gg * 64 + col],       c[mi][ni][0]);
            atomicAdd(&tok[bh * 4096 + gg * 64 + col + 1],   c[mi][ni][1]);
            atomicAdd(&tok[bh * 4096 + (gg + 8) * 64 + col],     c[mi][ni][2]);
            atomicAdd(&tok[bh * 4096 + (gg + 8) * 64 + col + 1], c[mi][ni][3]);
        }
    }
    atomicAdd(&cs[bh * 64 + gcs], csacc);
}

// ================= prep kernels =================
__global__ void presplit2(const float* __restrict__ X0, const float* __restrict__ X1) {
    const int blk = blockIdx.x;
    const float* X = (blk < 32768) ? X0 : X1;
    size_t li = (size_t)(blk & 32767) * 256 + threadIdx.x;
    size_t gi = (size_t)blk * 256 + threadIdx.x;
    float4 v = ((const float4*)X)[li];
    uint2 hh, ll;
    split2(v.x, v.y, hh.x, ll.x);
    split2(v.z, v.w, hh.y, ll.y);
    ((uint2*)d_xs_h)[gi] = hh;
    ((uint2*)d_xs_l)[gi] = ll;
}

// prep_wfx also zeroes the token accumulators (grid 512x256 == 131072 == BH*M*CH)
__global__ void prep_wfx(const float* __restrict__ W) {
    int j = blockIdx.x, cc = threadIdx.x;
    float wv = W[cc * 512 + j];
    __nv_bfloat16 h = __float2bfloat16(wv);
    d_wfx_h[j * 256 + cc] = h;
    d_wfx_l[j * 256 + cc] = __float2bfloat16(wv - __bfloat162float(h));
    int i = j * 256 + cc;
    d_tokx[i] = 0.f; d_tokc[i] = 0.f;
    if (i < BH_ * M_) { d_csx[i] = 0.f; d_csc[i] = 0.f; }
}

__global__ void prep_wls(const float* __restrict__ Wx, const float* __restrict__ Wslice,
                         const float* __restrict__ bx, const float* __restrict__ bslice) {
    extern __shared__ float sm[];
    float* ws = sm;
    float* wx = sm + 64;
    int j = blockIdx.x, h = j >> 6, m = j & 63, t = threadIdx.x;
    if (t < 64) ws[t] = Wslice[t * 64 + m];
    for (int i = t; i < 256 * 16; i += 256) {
        int r = i >> 4, q = i & 15;
        *(float4*)&wx[r * 68 + q * 4] = *(const float4*)&Wx[r * 512 + h * 64 + q * 4];
    }
    __syncthreads();
    float acc = 0.f;
#pragma unroll 8
    for (int e = 0; e < 64; e++) acc += wx[t * 68 + e] * ws[e];
    __nv_bfloat16 hh = __float2bfloat16(acc);
    d_wls_h[j * 256 + t] = hh;
    d_wls_l[j * 256 + t] = __float2bfloat16(acc - __bfloat162float(hh));
    if (t == 0) {
        float bb = bslice[m];
        for (int e = 0; e < 64; e++) bb += bx[h * 64 + e] * ws[e];
        d_bls[j] = bb;
    }
}

// ================= tiny attention + fused Wo refactor =================
__global__ void attn_kernel(const float* __restrict__ Wq,
                            const float* __restrict__ Wk,
                            const float* __restrict__ Wv) {
    extern __shared__ float sm[];
    float* A  = sm;
    float* Ks = sm + 64 * 65;
    float* Vs = Ks + 64 * 64;
    const int bh = blockIdx.x;
    const int g = threadIdx.x;

    for (int idx = g; idx < 4096; idx += 64) {
        int r = idx >> 6, cc = idx & 63;
        A[r * 65 + cc] = d_tokc[bh * 4096 + idx] / (d_csc[bh * 64 + r] + 1e-5f);
    }
    __syncthreads();
    {
        float ka[64], va[64];
#pragma unroll
        for (int cc = 0; cc < 64; cc++) { ka[cc] = 0.f; va[cc] = 0.f; }
        for (int e = 0; e < 64; e++) {
            float te = A[g * 65 + e];
#pragma unroll
            for (int cc = 0; cc < 64; cc++) {
                ka[cc] += te * Wk[e * 64 + cc];
                va[cc] += te * Wv[e * 64 + cc];
            }
        }
#pragma unroll
        for (int cc = 0; cc < 64; cc++) { Ks[g * 64 + cc] = ka[cc]; Vs[g * 64 + cc] = va[cc]; }
    }
    __syncthreads();
    for (int idx = g; idx < 4096; idx += 64) {
        int r = idx >> 6, cc = idx & 63;
        A[r * 65 + cc] = d_tokx[bh * 4096 + idx] / (d_csx[bh * 64 + r] + 1e-5f);
    }
    __syncthreads();

    float q[64];
#pragma unroll
    for (int cc = 0; cc < 64; cc++) q[cc] = 0.f;
    for (int e = 0; e < 64; e++) {
        float te = A[g * 65 + e];
#pragma unroll
        for (int cc = 0; cc < 64; cc++) q[cc] += te * Wq[e * 64 + cc];
    }
    __syncthreads();
    float* srow = &A[g * 65];
    float mx = -1e30f;
    for (int m = 0; m < 64; m++) {
        float a2 = 0.f;
#pragma unroll
        for (int cc = 0; cc < 64; cc++) a2 += q[cc] * Ks[m * 64 + cc];
        a2 *= 0.125f;
        srow[m] = a2;
        mx = fmaxf(mx, a2);
    }
    float sum = 0.f;
    for (int m = 0; m < 64; m++) { float e = __expf(srow[m] - mx); srow[m] = e; sum += e; }
    float inv = 1.f / sum;
    float o[64];
#pragma unroll
    for (int cc = 0; cc < 64; cc++) o[cc] = 0.f;
    for (int m = 0; m < 64; m++) {
        float p = srow[m] * inv;
#pragma unroll
        for (int cc = 0; cc < 64; cc++) o[cc] += p * Vs[m * 64 + cc];
    }
    float invx = 1.f / (d_csx[bh * 64 + g] + 1e-5f);
#pragma unroll
    for (int cc = 0; cc < 64; cc++) d_outsc[bh * 4096 + g * 64 + cc] = o[cc] * invx;
}

// wot + split-transpose fused: writes d_wot_h/l[b][cc][hg] directly
__global__ __launch_bounds__(256) void wot_kernel(const float* __restrict__ Wo) {
    const int bhg = blockIdx.x;                 // b*512 + hg
    const int b = bhg >> 9;
    const int hg = bhg & 511;
    const int h = hg >> 6;
    __shared__ float orow[64];
    const int t = threadIdx.x;
    if (t < 64) orow[t] = d_outsc[bhg * 64 + t];   // bhg*64 == (b*8+h)*4096 + g*64
    __syncthreads();
    float acc = 0.f;
#pragma unroll 8
    for (int cc = 0; cc < 64; cc++) acc += orow[cc] * Wo[(h * 64 + cc) * 256 + t];
    __nv_bfloat16 hh = __float2bfloat16(acc);
    d_wot_h[((size_t)b * 256 + t) * 512 + hg] = hh;
    d_wot_l[((size_t)b * 256 + t) * 512 + hg] = __float2bfloat16(acc - __bfloat162float(hh));
}

// ================= launcher =================
extern "C" void kernel_launch(void* const* d_in, const int* in_sizes, int n_in,
                              void* d_out, int out_size) {
    const float* x      = (const float*)d_in[0];
    const float* xc     = (const float*)d_in[1];
    const float* Wfx    = (const float*)d_in[2];
    const float* bfx    = (const float*)d_in[3];
    const float* Wx     = (const float*)d_in[4];
    const float* bx     = (const float*)d_in[5];
    const float* Wslice = (const float*)d_in[6];
    const float* bslice = (const float*)d_in[7];
    const float* temp   = (const float*)d_in[8];
    const float* Wq     = (const float*)d_in[9];
    const float* Wk     = (const float*)d_in[10];
    const float* Wv     = (const float*)d_in[11];
    const float* Wo     = (const float*)d_in[12];
    const float* bo     = (const float*)d_in[13];
    float* out = (float*)d_out;

    const int attn_smem = (64 * 65 + 2 * 64 * 64) * (int)sizeof(float);
    const int wls_smem  = (64 + 256 * 68) * (int)sizeof(float);
    cudaFuncSetAttribute(attn_kernel, cudaFuncAttributeMaxDynamicSharedMemorySize, attn_smem);
    cudaFuncSetAttribute(prep_wls,    cudaFuncAttributeMaxDynamicSharedMemorySize, wls_smem);
    cudaFuncSetAttribute(proj_mma,    cudaFuncAttributeMaxDynamicSharedMemorySize, GEMM_SMEM);
    cudaFuncSetAttribute(final_mma,   cudaFuncAttributeMaxDynamicSharedMemorySize, GEMM_SMEM);
    cudaFuncSetAttribute(token_mma,   cudaFuncAttributeMaxDynamicSharedMemorySize, TOK_SMEM);

    prep_wfx<<<512, 256>>>(Wfx);
    prep_wls<<<512, 256, wls_smem>>>(Wx, Wslice, bx, bslice);
    presplit2<<<65536, 256>>>(x, xc);
    proj_mma<<<dim3(8, 2 * ROWS_ / 128), 256, GEMM_SMEM>>>(bfx, temp);
    token_mma<<<dim3(16, 64), 256, TOK_SMEM>>>();
    attn_kernel<<<BH_, 64, attn_smem>>>(Wq, Wk, Wv);
    wot_kernel<<<B_ * INNER_, 256>>>(Wo);
    final_mma<<<dim3(2, ROWS_ / 128), 256, GEMM_SMEM>>>(bo, out);
}